// round 1
// baseline (speedup 1.0000x reference)
#include <cuda_runtime.h>

#define NN 100000
#define FD 128
#define NE 1600000
#define NG 64
#define NC 10

// ---------------- scratch (device globals; no allocation) ----------------
__device__ float g_T [(size_t)NN * FD];   // GEMM output (pre-aggregation)
__device__ float g_HA[(size_t)NN * FD];   // layer activations (ping)
__device__ float g_HB[(size_t)NN * FD];   // layer activations (pong)
__device__ float g_deg [NN];
__device__ float g_dinv[NN];
__device__ float g_sums[NG * FD];
__device__ float g_cnt [NG];
__device__ int   g_is64;                  // 1 if indices are int64, 0 if int32

__device__ __forceinline__ float* buf(int i) {
    return (i == 0) ? g_T : ((i == 1) ? g_HA : g_HB);
}

__device__ __forceinline__ int edge_src(const void* ei, int e) {
    return g_is64 ? (int)((const long long*)ei)[e] : ((const int*)ei)[e];
}
__device__ __forceinline__ int edge_dst(const void* ei, int e) {
    return g_is64 ? (int)((const long long*)ei)[(size_t)NE + e]
                  : ((const int*)ei)[(size_t)NE + e];
}
__device__ __forceinline__ int batch_at(const void* b, int v) {
    return g_is64 ? (int)((const long long*)b)[v] : ((const int*)b)[v];
}

// ---------------- dtype detection ----------------
// batch is sorted in [0, 64). If stored as int64 (little-endian), the odd
// 32-bit words of the first 100000 words are all high-words == 0.
// If stored as int32, odd words are batch values; the tail of the sorted
// array holds 63s, so nonzero odd words exist. Reads stay within the
// minimum guaranteed size (100000 * 4 bytes).
__global__ void detect_i64(const int* __restrict__ batch_words) {
    __shared__ int found;
    if (threadIdx.x == 0) found = 0;
    __syncthreads();
    int local = 0;
    for (int i = threadIdx.x; i < NN / 2; i += blockDim.x)
        if (batch_words[2 * i + 1] != 0) local = 1;
    if (local) atomicOr(&found, 1);
    __syncthreads();
    if (threadIdx.x == 0) g_is64 = (found == 0) ? 1 : 0;
}

// ---------------- degree / normalization ----------------
__global__ void deg_init() {
    int v = blockIdx.x * blockDim.x + threadIdx.x;
    if (v < NN) g_deg[v] = 1.0f;  // self-loop
}
__global__ void deg_count(const void* __restrict__ ei) {
    int e = blockIdx.x * blockDim.x + threadIdx.x;
    if (e < NE) atomicAdd(&g_deg[edge_dst(ei, e)], 1.0f);
}
__global__ void dinv_k() {
    int v = blockIdx.x * blockDim.x + threadIdx.x;
    if (v < NN) g_dinv[v] = rsqrtf(g_deg[v]);
}

__global__ void zero_pool() {
    int i = blockIdx.x * blockDim.x + threadIdx.x;
    if (i < NG * FD) g_sums[i] = 0.0f;
    if (i < NG) g_cnt[i] = 0.0f;
}

// ---------------- GEMM: T = relu?(X) @ W  (X: [n,128], W: [128,128]) ----------------
// Block: 256 threads, tile 64 rows x 128 cols, K chunked by 32.
// Micro-tile per thread: 8 rows x 4 cols.
__global__ void __launch_bounds__(256) gemm128(
    const float* __restrict__ Xext, int xsel, int dorelu,
    const float* __restrict__ W, int n)
{
    __shared__ float Ws[32 * 128];   // 16 KB
    __shared__ float Xs[64 * 36];    // padded stride 36 (16B-aligned rows)

    const float* X = (xsel < 0) ? Xext : buf(xsel);
    const int tid  = threadIdx.x;
    const int row0 = blockIdx.x * 64;
    const int rowg = tid >> 5;   // 0..7  (8 rows each)
    const int colg = tid & 31;   // 0..31 (4 cols each)

    float acc[8][4];
#pragma unroll
    for (int r = 0; r < 8; r++)
#pragma unroll
        for (int c = 0; c < 4; c++) acc[r][c] = 0.0f;

    for (int kc = 0; kc < 4; kc++) {
        // load W chunk [32 x 128]
#pragma unroll
        for (int q = 0; q < 4; q++) {
            int idx = tid + q * 256;       // float4 index, 0..1023
            int k  = idx >> 5;
            int cq = idx & 31;
            float4 w4 = *(const float4*)(W + (size_t)(kc * 32 + k) * 128 + cq * 4);
            *(float4*)(Ws + k * 128 + cq * 4) = w4;
        }
        // load X tile [64 x 32]
#pragma unroll
        for (int q = 0; q < 2; q++) {
            int idx = tid + q * 256;       // float4 index, 0..511
            int r  = idx >> 3;
            int kq = idx & 7;
            float4 xv = make_float4(0.f, 0.f, 0.f, 0.f);
            int grow = row0 + r;
            if (grow < n) {
                xv = *(const float4*)(X + (size_t)grow * 128 + kc * 32 + kq * 4);
                if (dorelu) {
                    xv.x = fmaxf(xv.x, 0.f); xv.y = fmaxf(xv.y, 0.f);
                    xv.z = fmaxf(xv.z, 0.f); xv.w = fmaxf(xv.w, 0.f);
                }
            }
            *(float4*)(Xs + r * 36 + kq * 4) = xv;
        }
        __syncthreads();

#pragma unroll
        for (int k = 0; k < 32; k++) {
            float4 w4 = *(const float4*)(Ws + k * 128 + colg * 4);
#pragma unroll
            for (int r = 0; r < 8; r++) {
                float xv = Xs[(rowg * 8 + r) * 36 + k];  // warp-broadcast
                acc[r][0] = fmaf(xv, w4.x, acc[r][0]);
                acc[r][1] = fmaf(xv, w4.y, acc[r][1]);
                acc[r][2] = fmaf(xv, w4.z, acc[r][2]);
                acc[r][3] = fmaf(xv, w4.w, acc[r][3]);
            }
        }
        __syncthreads();
    }

#pragma unroll
    for (int r = 0; r < 8; r++) {
        int grow = row0 + rowg * 8 + r;
        if (grow < n) {
            float4 o = make_float4(acc[r][0], acc[r][1], acc[r][2], acc[r][3]);
            *(float4*)(g_T + (size_t)grow * 128 + colg * 4) = o;
        }
    }
}

// ---------------- self-loop + bias: Y = T * dinv^2 + b ----------------
__global__ void selfloop_bias(int ysel, const float* __restrict__ b) {
    int idx = blockIdx.x * blockDim.x + threadIdx.x;  // over NN*32 float4 slots
    if (idx >= NN * 32) return;
    int v = idx >> 5, q = idx & 31;
    float di = g_dinv[v];
    float c = di * di;
    float4 t  = *(const float4*)(g_T + (size_t)v * 128 + q * 4);
    float4 bb = *(const float4*)(b + q * 4);
    float4 o;
    o.x = fmaf(t.x, c, bb.x);
    o.y = fmaf(t.y, c, bb.y);
    o.z = fmaf(t.z, c, bb.z);
    o.w = fmaf(t.w, c, bb.w);
    *(float4*)(buf(ysel) + (size_t)v * 128 + q * 4) = o;
}

// ---------------- edge scatter: Y[dst] += T[src] * dinv[src]*dinv[dst] ----------------
// warp-per-edge, lane handles one float4 (4 features)
__global__ void __launch_bounds__(256) scatter_edges(int ysel, const void* __restrict__ ei) {
    int idx = blockIdx.x * blockDim.x + threadIdx.x;  // NE*32 = 51.2M < 2^31
    if (idx >= NE * 32) return;
    int e = idx >> 5, q = idx & 31;
    int s = edge_src(ei, e);
    int d = edge_dst(ei, e);
    float nrm = g_dinv[s] * g_dinv[d];
    float4 t = *(const float4*)(g_T + (size_t)s * 128 + q * 4);
    float* y = buf(ysel) + (size_t)d * 128 + q * 4;
    atomicAdd(y + 0, t.x * nrm);
    atomicAdd(y + 1, t.y * nrm);
    atomicAdd(y + 2, t.z * nrm);
    atomicAdd(y + 3, t.w * nrm);
}

// ---------------- pooling: segment sums over sorted batch ----------------
// Block handles 256 nodes, 128 threads (one per feature), running-sum flush
// on segment boundary -> ~1 atomic per feature per block.
__global__ void __launch_bounds__(128) pool_accum(int ysel, const void* __restrict__ batch, int n) {
    __shared__ int sb[256];
    int f  = threadIdx.x;
    int v0 = blockIdx.x * 256;
    for (int i = f; i < 256; i += 128) {
        int v = v0 + i;
        sb[i] = (v < n) ? batch_at(batch, v) : -1;
    }
    __syncthreads();
    const float* Y = buf(ysel);
    float acc = 0.f, ccnt = 0.f;
    int curg = -1;
    for (int i = 0; i < 256; i++) {
        int g = sb[i];
        if (g < 0) break;
        if (g != curg) {
            if (curg >= 0) {
                atomicAdd(&g_sums[curg * FD + f], acc);
                if (f == 0) atomicAdd(&g_cnt[curg], ccnt);
            }
            acc = 0.f; ccnt = 0.f; curg = g;
        }
        acc  += Y[(size_t)(v0 + i) * FD + f];
        ccnt += 1.f;
    }
    if (curg >= 0) {
        atomicAdd(&g_sums[curg * FD + f], acc);
        if (f == 0) atomicAdd(&g_cnt[curg], ccnt);
    }
}

// ---------------- finalize: emb = sums/cnt ; logits = emb @ Wlin + blin ----------------
__global__ void __launch_bounds__(128) finalize(
    const float* __restrict__ Wlin, const float* __restrict__ blin,
    float* __restrict__ out, int out_size)
{
    int g = blockIdx.x;
    int f = threadIdx.x;
    __shared__ float se[FD];
    float e = g_sums[g * FD + f] / fmaxf(g_cnt[g], 1.0f);
    se[f] = e;
    if (out_size >= NG * NC + NG * FD)
        out[NG * NC + g * FD + f] = e;   // emb after logits
    __syncthreads();
    if (f < NC) {
        float s = blin[f];
#pragma unroll
        for (int k = 0; k < FD; k++)
            s = fmaf(se[k], Wlin[k * NC + f], s);
        out[g * NC + f] = s;
    }
}

// ---------------- launch ----------------
extern "C" void kernel_launch(void* const* d_in, const int* in_sizes, int n_in,
                              void* d_out, int out_size) {
    const float* x    = (const float*)d_in[0];
    const void*  ei   = d_in[1];               // edge_index [2, NE], int32 or int64
    const void*  batch= d_in[2];               // [NN], int32 or int64
    const float* W1   = (const float*)d_in[3];
    const float* b1   = (const float*)d_in[4];
    const float* W2   = (const float*)d_in[5];
    const float* b2   = (const float*)d_in[6];
    const float* W3   = (const float*)d_in[7];
    const float* b3   = (const float*)d_in[8];
    const float* Wlin = (const float*)d_in[9];
    const float* blin = (const float*)d_in[10];
    float* out = (float*)d_out;
    const int n = NN;

    detect_i64<<<1, 256>>>((const int*)batch);

    deg_init <<<(NN + 255) / 256, 256>>>();
    deg_count<<<(NE + 255) / 256, 256>>>(ei);
    dinv_k   <<<(NN + 255) / 256, 256>>>();
    zero_pool<<<(NG * FD + 255) / 256, 256>>>();

    const int gemm_grid  = (NN + 63) / 64;
    const int sl_grid    = (NN * 32 + 255) / 256;
    const int sc_grid    = (int)(((long long)NE * 32 + 255) / 256);

    // Layer 1: x -> T -> HA
    gemm128      <<<gemm_grid, 256>>>(x, -1, 0, W1, n);
    selfloop_bias<<<sl_grid, 256>>>(1, b1);
    scatter_edges<<<sc_grid, 256>>>(1, ei);

    // Layer 2: relu(HA) -> T -> HB
    gemm128      <<<gemm_grid, 256>>>(nullptr, 1, 1, W2, n);
    selfloop_bias<<<sl_grid, 256>>>(2, b2);
    scatter_edges<<<sc_grid, 256>>>(2, ei);

    // Layer 3: relu(HB) -> T -> HA
    gemm128      <<<gemm_grid, 256>>>(nullptr, 2, 1, W3, n);
    selfloop_bias<<<sl_grid, 256>>>(1, b3);
    scatter_edges<<<sc_grid, 256>>>(1, ei);

    // Pool + head
    pool_accum<<<(NN + 255) / 256, 128>>>(1, batch, n);
    finalize  <<<NG, 128>>>(Wlin, blin, out, out_size);
}

// round 2
// speedup vs baseline: 2.7840x; 2.7840x over previous
#include <cuda_runtime.h>

#define NN 100000
#define FD 128
#define NE 1600000
#define NG 64
#define NC 10
#define SCAN_CHUNK 1024
#define SCAN_BLOCKS ((NN + SCAN_CHUNK - 1) / SCAN_CHUNK)   // 98

// ---------------- scratch (device globals; no allocation) ----------------
__device__ float  g_T [(size_t)NN * FD];   // GEMM output (pre-aggregation)
__device__ float  g_HA[(size_t)NN * FD];   // layer activations (ping)
__device__ float  g_HB[(size_t)NN * FD];   // layer activations (pong)
__device__ float  g_dinv[NN];
__device__ int    g_cntN[NN];              // in-degree counts (no self-loop)
__device__ int    g_rowptr[NN + 1];
__device__ int    g_pos[NN];
__device__ int    g_bsum[128];
__device__ float2 g_sw[NE];                // .x = src (bits), .y = edge weight
__device__ float  g_sums[NG * FD];
__device__ float  g_cnt [NG];
__device__ int    g_is64;

__device__ __forceinline__ float* buf(int i) {
    return (i == 0) ? g_T : ((i == 1) ? g_HA : g_HB);
}
__device__ __forceinline__ int edge_src(const void* ei, int e) {
    return g_is64 ? (int)((const long long*)ei)[e] : ((const int*)ei)[e];
}
__device__ __forceinline__ int edge_dst(const void* ei, int e) {
    return g_is64 ? (int)((const long long*)ei)[(size_t)NE + e]
                  : ((const int*)ei)[(size_t)NE + e];
}
__device__ __forceinline__ int batch_at(const void* b, int v) {
    return g_is64 ? (int)((const long long*)b)[v] : ((const int*)b)[v];
}

// ---------------- dtype detection (batch sorted in [0,64)) ----------------
__global__ void detect_i64(const int* __restrict__ batch_words) {
    __shared__ int found;
    if (threadIdx.x == 0) found = 0;
    __syncthreads();
    int local = 0;
    for (int i = threadIdx.x; i < NN / 2; i += blockDim.x)
        if (batch_words[2 * i + 1] != 0) local = 1;
    if (local) atomicOr(&found, 1);
    __syncthreads();
    if (threadIdx.x == 0) g_is64 = (found == 0) ? 1 : 0;
}

// ---------------- degree / CSR build ----------------
__global__ void zero_counts() {
    int v = blockIdx.x * blockDim.x + threadIdx.x;
    if (v < NN) g_cntN[v] = 0;
}
__global__ void count_edges(const void* __restrict__ ei) {
    int e = blockIdx.x * blockDim.x + threadIdx.x;
    if (e < NE) atomicAdd(&g_cntN[edge_dst(ei, e)], 1);
}
__global__ void dinv_k() {
    int v = blockIdx.x * blockDim.x + threadIdx.x;
    if (v < NN) g_dinv[v] = rsqrtf((float)(g_cntN[v] + 1));  // +1 self-loop
}

// exclusive scan of g_cntN -> g_rowptr (3 phases)
__global__ void __launch_bounds__(256) scan1() {
    __shared__ int warp_tot[8];
    int base = blockIdx.x * SCAN_CHUNK + threadIdx.x * 4;
    int lane = threadIdx.x & 31, w = threadIdx.x >> 5;
    int v0 = (base + 0 < NN) ? g_cntN[base + 0] : 0;
    int v1 = (base + 1 < NN) ? g_cntN[base + 1] : 0;
    int v2 = (base + 2 < NN) ? g_cntN[base + 2] : 0;
    int v3 = (base + 3 < NN) ? g_cntN[base + 3] : 0;
    int tot = v0 + v1 + v2 + v3;
    int inc = tot;
#pragma unroll
    for (int o = 1; o < 32; o <<= 1) {
        int t = __shfl_up_sync(~0u, inc, o);
        if (lane >= o) inc += t;
    }
    if (lane == 31) warp_tot[w] = inc;
    __syncthreads();
    if (w == 0 && lane < 8) {
        int t = warp_tot[lane];
#pragma unroll
        for (int o = 1; o < 8; o <<= 1) {
            int u = __shfl_up_sync(0xffu, t, o);
            if (lane >= o) t += u;
        }
        warp_tot[lane] = t;
    }
    __syncthreads();
    int excl = ((w > 0) ? warp_tot[w - 1] : 0) + (inc - tot);
    if (base + 0 < NN) g_rowptr[base + 0] = excl;
    if (base + 1 < NN) g_rowptr[base + 1] = excl + v0;
    if (base + 2 < NN) g_rowptr[base + 2] = excl + v0 + v1;
    if (base + 3 < NN) g_rowptr[base + 3] = excl + v0 + v1 + v2;
    if (threadIdx.x == 255) g_bsum[blockIdx.x] = warp_tot[7];
}
__global__ void __launch_bounds__(128) scan2() {
    __shared__ int wt[4];
    int tid = threadIdx.x, lane = tid & 31, w = tid >> 5;
    int v = (tid < SCAN_BLOCKS) ? g_bsum[tid] : 0;
    int inc = v;
#pragma unroll
    for (int o = 1; o < 32; o <<= 1) {
        int t = __shfl_up_sync(~0u, inc, o);
        if (lane >= o) inc += t;
    }
    if (lane == 31) wt[w] = inc;
    __syncthreads();
    if (w == 0 && lane < 4) {
        int t = wt[lane];
#pragma unroll
        for (int o = 1; o < 4; o <<= 1) {
            int u = __shfl_up_sync(0xfu, t, o);
            if (lane >= o) t += u;
        }
        wt[lane] = t;
    }
    __syncthreads();
    int excl = ((w > 0) ? wt[w - 1] : 0) + (inc - v);
    if (tid < SCAN_BLOCKS) g_bsum[tid] = excl;
    if (tid == 0) g_rowptr[NN] = NE;
}
__global__ void __launch_bounds__(256) scan3() {
    int off = g_bsum[blockIdx.x];
    int base = blockIdx.x * SCAN_CHUNK + threadIdx.x * 4;
#pragma unroll
    for (int j = 0; j < 4; j++) {
        int idx = base + j;
        if (idx < NN) {
            int val = g_rowptr[idx] + off;
            g_rowptr[idx] = val;
            g_pos[idx] = val;
        }
    }
}
__global__ void fill_csr(const void* __restrict__ ei) {
    int e = blockIdx.x * blockDim.x + threadIdx.x;
    if (e >= NE) return;
    int s = edge_src(ei, e);
    int d = edge_dst(ei, e);
    int p = atomicAdd(&g_pos[d], 1);
    g_sw[p] = make_float2(__int_as_float(s), g_dinv[s] * g_dinv[d]);
}

__global__ void zero_pool() {
    int i = blockIdx.x * blockDim.x + threadIdx.x;
    if (i < NG * FD) g_sums[i] = 0.0f;
    if (i < NG) g_cnt[i] = 0.0f;
}

// ---------------- GEMM: T = relu?(X) @ W ----------------
__global__ void __launch_bounds__(256) gemm128(
    const float* __restrict__ Xext, int xsel, int dorelu,
    const float* __restrict__ W, int n)
{
    __shared__ float Ws[32 * 128];
    __shared__ float Xs[64 * 36];

    const float* X = (xsel < 0) ? Xext : buf(xsel);
    const int tid  = threadIdx.x;
    const int row0 = blockIdx.x * 64;
    const int rowg = tid >> 5;
    const int colg = tid & 31;

    float acc[8][4];
#pragma unroll
    for (int r = 0; r < 8; r++)
#pragma unroll
        for (int c = 0; c < 4; c++) acc[r][c] = 0.0f;

    for (int kc = 0; kc < 4; kc++) {
#pragma unroll
        for (int q = 0; q < 4; q++) {
            int idx = tid + q * 256;
            int k = idx >> 5, cq = idx & 31;
            float4 w4 = *(const float4*)(W + (size_t)(kc * 32 + k) * 128 + cq * 4);
            *(float4*)(Ws + k * 128 + cq * 4) = w4;
        }
#pragma unroll
        for (int q = 0; q < 2; q++) {
            int idx = tid + q * 256;
            int r = idx >> 3, kq = idx & 7;
            float4 xv = make_float4(0.f, 0.f, 0.f, 0.f);
            int grow = row0 + r;
            if (grow < n) {
                xv = *(const float4*)(X + (size_t)grow * 128 + kc * 32 + kq * 4);
                if (dorelu) {
                    xv.x = fmaxf(xv.x, 0.f); xv.y = fmaxf(xv.y, 0.f);
                    xv.z = fmaxf(xv.z, 0.f); xv.w = fmaxf(xv.w, 0.f);
                }
            }
            *(float4*)(Xs + r * 36 + kq * 4) = xv;
        }
        __syncthreads();

#pragma unroll
        for (int k = 0; k < 32; k++) {
            float4 w4 = *(const float4*)(Ws + k * 128 + colg * 4);
#pragma unroll
            for (int r = 0; r < 8; r++) {
                float xv = Xs[(rowg * 8 + r) * 36 + k];
                acc[r][0] = fmaf(xv, w4.x, acc[r][0]);
                acc[r][1] = fmaf(xv, w4.y, acc[r][1]);
                acc[r][2] = fmaf(xv, w4.z, acc[r][2]);
                acc[r][3] = fmaf(xv, w4.w, acc[r][3]);
            }
        }
        __syncthreads();
    }

#pragma unroll
    for (int r = 0; r < 8; r++) {
        int grow = row0 + rowg * 8 + r;
        if (grow < n) {
            float4 o = make_float4(acc[r][0], acc[r][1], acc[r][2], acc[r][3]);
            *(float4*)(g_T + (size_t)grow * 128 + colg * 4) = o;
        }
    }
}

// ---------------- fused aggregation: Y[v] = b + T[v]*dinv[v]^2 + sum_e w*T[src]
// warp per node, lane handles one float4 (4 features). Unroll-4 gathers (MLP=4).
__global__ void __launch_bounds__(256) aggregate(int ysel, const float* __restrict__ bias) {
    int warp = (blockIdx.x * 256 + threadIdx.x) >> 5;
    if (warp >= NN) return;
    int lane = threadIdx.x & 31;
    int beg = g_rowptr[warp], end = g_rowptr[warp + 1];
    float di = g_dinv[warp];
    float c = di * di;
    float4 t  = *(const float4*)(g_T + (size_t)warp * 128 + lane * 4);
    float4 bb = *(const float4*)(bias + lane * 4);
    float ax = fmaf(t.x, c, bb.x);
    float ay = fmaf(t.y, c, bb.y);
    float az = fmaf(t.z, c, bb.z);
    float aw = fmaf(t.w, c, bb.w);

    int i = beg;
    for (; i + 4 <= end; i += 4) {
        float2 e0 = g_sw[i + 0];
        float2 e1 = g_sw[i + 1];
        float2 e2 = g_sw[i + 2];
        float2 e3 = g_sw[i + 3];
        const float4 t0 = *(const float4*)(g_T + (size_t)__float_as_int(e0.x) * 128 + lane * 4);
        const float4 t1 = *(const float4*)(g_T + (size_t)__float_as_int(e1.x) * 128 + lane * 4);
        const float4 t2 = *(const float4*)(g_T + (size_t)__float_as_int(e2.x) * 128 + lane * 4);
        const float4 t3 = *(const float4*)(g_T + (size_t)__float_as_int(e3.x) * 128 + lane * 4);
        ax = fmaf(t0.x, e0.y, ax); ay = fmaf(t0.y, e0.y, ay);
        az = fmaf(t0.z, e0.y, az); aw = fmaf(t0.w, e0.y, aw);
        ax = fmaf(t1.x, e1.y, ax); ay = fmaf(t1.y, e1.y, ay);
        az = fmaf(t1.z, e1.y, az); aw = fmaf(t1.w, e1.y, aw);
        ax = fmaf(t2.x, e2.y, ax); ay = fmaf(t2.y, e2.y, ay);
        az = fmaf(t2.z, e2.y, az); aw = fmaf(t2.w, e2.y, aw);
        ax = fmaf(t3.x, e3.y, ax); ay = fmaf(t3.y, e3.y, ay);
        az = fmaf(t3.z, e3.y, az); aw = fmaf(t3.w, e3.y, aw);
    }
    for (; i < end; i++) {
        float2 e0 = g_sw[i];
        const float4 t0 = *(const float4*)(g_T + (size_t)__float_as_int(e0.x) * 128 + lane * 4);
        ax = fmaf(t0.x, e0.y, ax); ay = fmaf(t0.y, e0.y, ay);
        az = fmaf(t0.z, e0.y, az); aw = fmaf(t0.w, e0.y, aw);
    }
    float4 o = make_float4(ax, ay, az, aw);
    *(float4*)(buf(ysel) + (size_t)warp * 128 + lane * 4) = o;
}

// ---------------- pooling ----------------
__global__ void __launch_bounds__(128) pool_accum(int ysel, const void* __restrict__ batch, int n) {
    __shared__ int sb[256];
    int f  = threadIdx.x;
    int v0 = blockIdx.x * 256;
    for (int i = f; i < 256; i += 128) {
        int v = v0 + i;
        sb[i] = (v < n) ? batch_at(batch, v) : -1;
    }
    __syncthreads();
    const float* Y = buf(ysel);
    float acc = 0.f, ccnt = 0.f;
    int curg = -1;
    for (int i = 0; i < 256; i++) {
        int g = sb[i];
        if (g < 0) break;
        if (g != curg) {
            if (curg >= 0) {
                atomicAdd(&g_sums[curg * FD + f], acc);
                if (f == 0) atomicAdd(&g_cnt[curg], ccnt);
            }
            acc = 0.f; ccnt = 0.f; curg = g;
        }
        acc  += Y[(size_t)(v0 + i) * FD + f];
        ccnt += 1.f;
    }
    if (curg >= 0) {
        atomicAdd(&g_sums[curg * FD + f], acc);
        if (f == 0) atomicAdd(&g_cnt[curg], ccnt);
    }
}

// ---------------- finalize ----------------
__global__ void __launch_bounds__(128) finalize(
    const float* __restrict__ Wlin, const float* __restrict__ blin,
    float* __restrict__ out, int out_size)
{
    int g = blockIdx.x;
    int f = threadIdx.x;
    __shared__ float se[FD];
    float e = g_sums[g * FD + f] / fmaxf(g_cnt[g], 1.0f);
    se[f] = e;
    if (out_size >= NG * NC + NG * FD)
        out[NG * NC + g * FD + f] = e;
    __syncthreads();
    if (f < NC) {
        float s = blin[f];
#pragma unroll
        for (int k = 0; k < FD; k++)
            s = fmaf(se[k], Wlin[k * NC + f], s);
        out[g * NC + f] = s;
    }
}

// ---------------- launch ----------------
extern "C" void kernel_launch(void* const* d_in, const int* in_sizes, int n_in,
                              void* d_out, int out_size) {
    const float* x    = (const float*)d_in[0];
    const void*  ei   = d_in[1];
    const void*  batch= d_in[2];
    const float* W1   = (const float*)d_in[3];
    const float* b1   = (const float*)d_in[4];
    const float* W2   = (const float*)d_in[5];
    const float* b2   = (const float*)d_in[6];
    const float* W3   = (const float*)d_in[7];
    const float* b3   = (const float*)d_in[8];
    const float* Wlin = (const float*)d_in[9];
    const float* blin = (const float*)d_in[10];
    float* out = (float*)d_out;
    const int n = NN;

    detect_i64 <<<1, 256>>>((const int*)batch);
    zero_counts<<<(NN + 255) / 256, 256>>>();
    count_edges<<<(NE + 255) / 256, 256>>>(ei);
    dinv_k     <<<(NN + 255) / 256, 256>>>();
    scan1      <<<SCAN_BLOCKS, 256>>>();
    scan2      <<<1, 128>>>();
    scan3      <<<SCAN_BLOCKS, 256>>>();
    fill_csr   <<<(NE + 255) / 256, 256>>>(ei);
    zero_pool  <<<(NG * FD + 255) / 256, 256>>>();

    const int gemm_grid = (NN + 63) / 64;
    const int agg_grid  = (NN * 32 + 255) / 256;

    // Layer 1: x -> T -> HA
    gemm128  <<<gemm_grid, 256>>>(x, -1, 0, W1, n);
    aggregate<<<agg_grid, 256>>>(1, b1);
    // Layer 2: relu(HA) -> T -> HB
    gemm128  <<<gemm_grid, 256>>>(nullptr, 1, 1, W2, n);
    aggregate<<<agg_grid, 256>>>(2, b2);
    // Layer 3: relu(HB) -> T -> HA
    gemm128  <<<gemm_grid, 256>>>(nullptr, 2, 1, W3, n);
    aggregate<<<agg_grid, 256>>>(1, b3);

    pool_accum<<<(NN + 255) / 256, 128>>>(1, batch, n);
    finalize  <<<NG, 128>>>(Wlin, blin, out, out_size);
}

// round 3
// speedup vs baseline: 3.1133x; 1.1183x over previous
#include <cuda_runtime.h>
#include <cuda_fp16.h>

#define NN 100000
#define FD 128
#define NE 1600000
#define NG 64
#define NC 10
#define SCAN_CHUNK 1024
#define SCAN_BLOCKS ((NN + SCAN_CHUNK - 1) / SCAN_CHUNK)   // 98

// ---------------- scratch (device globals; no allocation) ----------------
__device__ __half  g_Th[(size_t)NN * FD];  // GEMM output (half, gather source)
__device__ float   g_HA[(size_t)NN * FD];  // layer activations (ping)
__device__ float   g_HB[(size_t)NN * FD];  // layer activations (pong)
__device__ float   g_dinv[NN];
__device__ int     g_cntN[NN];
__device__ int     g_rowptr[NN + 1];
__device__ int     g_pos[NN];
__device__ int     g_bsum[128];
__device__ float2  g_sw[NE];               // .x = src (bits), .y = edge weight
__device__ float   g_sums[NG * FD];
__device__ float   g_cnt [NG];
__device__ int     g_is64;

__device__ __forceinline__ float* buf(int i) { return (i == 1) ? g_HA : g_HB; }

__device__ __forceinline__ int edge_src(const void* ei, int e) {
    return g_is64 ? (int)((const long long*)ei)[e] : ((const int*)ei)[e];
}
__device__ __forceinline__ int edge_dst(const void* ei, int e) {
    return g_is64 ? (int)((const long long*)ei)[(size_t)NE + e]
                  : ((const int*)ei)[(size_t)NE + e];
}
__device__ __forceinline__ int batch_at(const void* b, int v) {
    return g_is64 ? (int)((const long long*)b)[v] : ((const int*)b)[v];
}

// ---------------- dtype detection (batch sorted in [0,64)) ----------------
__global__ void detect_i64(const int* __restrict__ batch_words) {
    __shared__ int found;
    if (threadIdx.x == 0) found = 0;
    __syncthreads();
    int local = 0;
    for (int i = threadIdx.x; i < NN / 2; i += blockDim.x)
        if (batch_words[2 * i + 1] != 0) local = 1;
    if (local) atomicOr(&found, 1);
    __syncthreads();
    if (threadIdx.x == 0) g_is64 = (found == 0) ? 1 : 0;
}

// ---------------- zero init (counts + pool) ----------------
__global__ void zero_init() {
    int i = blockIdx.x * blockDim.x + threadIdx.x;
    if (i < NN) g_cntN[i] = 0;
    if (i < NG * FD) g_sums[i] = 0.0f;
    if (i < NG) g_cnt[i] = 0.0f;
}
__global__ void count_edges(const void* __restrict__ ei) {
    int e = blockIdx.x * blockDim.x + threadIdx.x;
    if (e < NE) atomicAdd(&g_cntN[edge_dst(ei, e)], 1);
}
__global__ void dinv_k() {
    int v = blockIdx.x * blockDim.x + threadIdx.x;
    if (v < NN) g_dinv[v] = rsqrtf((float)(g_cntN[v] + 1));
}

// exclusive scan of g_cntN -> g_rowptr (3 phases)
__global__ void __launch_bounds__(256) scan1() {
    __shared__ int warp_tot[8];
    int base = blockIdx.x * SCAN_CHUNK + threadIdx.x * 4;
    int lane = threadIdx.x & 31, w = threadIdx.x >> 5;
    int v0 = (base + 0 < NN) ? g_cntN[base + 0] : 0;
    int v1 = (base + 1 < NN) ? g_cntN[base + 1] : 0;
    int v2 = (base + 2 < NN) ? g_cntN[base + 2] : 0;
    int v3 = (base + 3 < NN) ? g_cntN[base + 3] : 0;
    int tot = v0 + v1 + v2 + v3;
    int inc = tot;
#pragma unroll
    for (int o = 1; o < 32; o <<= 1) {
        int t = __shfl_up_sync(~0u, inc, o);
        if (lane >= o) inc += t;
    }
    if (lane == 31) warp_tot[w] = inc;
    __syncthreads();
    if (w == 0 && lane < 8) {
        int t = warp_tot[lane];
#pragma unroll
        for (int o = 1; o < 8; o <<= 1) {
            int u = __shfl_up_sync(0xffu, t, o);
            if (lane >= o) t += u;
        }
        warp_tot[lane] = t;
    }
    __syncthreads();
    int excl = ((w > 0) ? warp_tot[w - 1] : 0) + (inc - tot);
    if (base + 0 < NN) g_rowptr[base + 0] = excl;
    if (base + 1 < NN) g_rowptr[base + 1] = excl + v0;
    if (base + 2 < NN) g_rowptr[base + 2] = excl + v0 + v1;
    if (base + 3 < NN) g_rowptr[base + 3] = excl + v0 + v1 + v2;
    if (threadIdx.x == 255) g_bsum[blockIdx.x] = warp_tot[7];
}
__global__ void __launch_bounds__(128) scan2() {
    __shared__ int wt[4];
    int tid = threadIdx.x, lane = tid & 31, w = tid >> 5;
    int v = (tid < SCAN_BLOCKS) ? g_bsum[tid] : 0;
    int inc = v;
#pragma unroll
    for (int o = 1; o < 32; o <<= 1) {
        int t = __shfl_up_sync(~0u, inc, o);
        if (lane >= o) inc += t;
    }
    if (lane == 31) wt[w] = inc;
    __syncthreads();
    if (w == 0 && lane < 4) {
        int t = wt[lane];
#pragma unroll
        for (int o = 1; o < 4; o <<= 1) {
            int u = __shfl_up_sync(0xfu, t, o);
            if (lane >= o) t += u;
        }
        wt[lane] = t;
    }
    __syncthreads();
    int excl = ((w > 0) ? wt[w - 1] : 0) + (inc - v);
    if (tid < SCAN_BLOCKS) g_bsum[tid] = excl;
    if (tid == 0) g_rowptr[NN] = NE;
}
__global__ void __launch_bounds__(256) scan3() {
    int off = g_bsum[blockIdx.x];
    int base = blockIdx.x * SCAN_CHUNK + threadIdx.x * 4;
#pragma unroll
    for (int j = 0; j < 4; j++) {
        int idx = base + j;
        if (idx < NN) {
            int val = g_rowptr[idx] + off;
            g_rowptr[idx] = val;
            g_pos[idx] = val;
        }
    }
}
__global__ void fill_csr(const void* __restrict__ ei) {
    int e = blockIdx.x * blockDim.x + threadIdx.x;
    if (e >= NE) return;
    int s = edge_src(ei, e);
    int d = edge_dst(ei, e);
    int p = atomicAdd(&g_pos[d], 1);
    g_sw[p] = make_float2(__int_as_float(s), g_dinv[s] * g_dinv[d]);
}

// ---------------- GEMM: Th = half(relu?(X) @ W) ----------------
__global__ void __launch_bounds__(256) gemm128(
    const float* __restrict__ Xext, int xsel, int dorelu,
    const float* __restrict__ W, int n)
{
    __shared__ float Ws[32 * 128];
    __shared__ float Xs[64 * 36];

    const float* X = (xsel < 0) ? Xext : buf(xsel);
    const int tid  = threadIdx.x;
    const int row0 = blockIdx.x * 64;
    const int rowg = tid >> 5;
    const int colg = tid & 31;

    float acc[8][4];
#pragma unroll
    for (int r = 0; r < 8; r++)
#pragma unroll
        for (int c = 0; c < 4; c++) acc[r][c] = 0.0f;

    for (int kc = 0; kc < 4; kc++) {
#pragma unroll
        for (int q = 0; q < 4; q++) {
            int idx = tid + q * 256;
            int k = idx >> 5, cq = idx & 31;
            float4 w4 = *(const float4*)(W + (size_t)(kc * 32 + k) * 128 + cq * 4);
            *(float4*)(Ws + k * 128 + cq * 4) = w4;
        }
#pragma unroll
        for (int q = 0; q < 2; q++) {
            int idx = tid + q * 256;
            int r = idx >> 3, kq = idx & 7;
            float4 xv = make_float4(0.f, 0.f, 0.f, 0.f);
            int grow = row0 + r;
            if (grow < n) {
                xv = *(const float4*)(X + (size_t)grow * 128 + kc * 32 + kq * 4);
                if (dorelu) {
                    xv.x = fmaxf(xv.x, 0.f); xv.y = fmaxf(xv.y, 0.f);
                    xv.z = fmaxf(xv.z, 0.f); xv.w = fmaxf(xv.w, 0.f);
                }
            }
            *(float4*)(Xs + r * 36 + kq * 4) = xv;
        }
        __syncthreads();

#pragma unroll
        for (int k = 0; k < 32; k++) {
            float4 w4 = *(const float4*)(Ws + k * 128 + colg * 4);
#pragma unroll
            for (int r = 0; r < 8; r++) {
                float xv = Xs[(rowg * 8 + r) * 36 + k];
                acc[r][0] = fmaf(xv, w4.x, acc[r][0]);
                acc[r][1] = fmaf(xv, w4.y, acc[r][1]);
                acc[r][2] = fmaf(xv, w4.z, acc[r][2]);
                acc[r][3] = fmaf(xv, w4.w, acc[r][3]);
            }
        }
        __syncthreads();
    }

#pragma unroll
    for (int r = 0; r < 8; r++) {
        int grow = row0 + rowg * 8 + r;
        if (grow < n) {
            __half2 p0 = __floats2half2_rn(acc[r][0], acc[r][1]);
            __half2 p1 = __floats2half2_rn(acc[r][2], acc[r][3]);
            uint2 u;
            u.x = *(unsigned int*)&p0;
            u.y = *(unsigned int*)&p1;
            *(uint2*)(g_Th + (size_t)grow * 128 + colg * 4) = u;
        }
    }
}

// ---------------- fused aggregation (half gathers, fp32 accum) ----------------
// Y[v] = b + Th[v]*dinv[v]^2 + sum_e w*Th[src]; warp per node, lane = 4 feats.
__device__ __forceinline__ void acc4(float& ax, float& ay, float& az, float& aw,
                                     uint2 u, float wgt) {
    __half2 h0 = *reinterpret_cast<__half2*>(&u.x);
    __half2 h1 = *reinterpret_cast<__half2*>(&u.y);
    float2 f0 = __half22float2(h0);
    float2 f1 = __half22float2(h1);
    ax = fmaf(f0.x, wgt, ax); ay = fmaf(f0.y, wgt, ay);
    az = fmaf(f1.x, wgt, az); aw = fmaf(f1.y, wgt, aw);
}

__global__ void __launch_bounds__(256) aggregate(int ysel, const float* __restrict__ bias) {
    int warp = (blockIdx.x * 256 + threadIdx.x) >> 5;
    if (warp >= NN) return;
    int lane = threadIdx.x & 31;
    int beg = g_rowptr[warp], end = g_rowptr[warp + 1];
    float di = g_dinv[warp];
    float c = di * di;
    float4 bb = *(const float4*)(bias + lane * 4);
    float ax = bb.x, ay = bb.y, az = bb.z, aw = bb.w;
    {
        uint2 u = *(const uint2*)(g_Th + (size_t)warp * 128 + lane * 4);
        acc4(ax, ay, az, aw, u, c);
    }

    int i = beg;
    for (; i + 4 <= end; i += 4) {
        float2 e0 = g_sw[i + 0];
        float2 e1 = g_sw[i + 1];
        float2 e2 = g_sw[i + 2];
        float2 e3 = g_sw[i + 3];
        uint2 u0 = *(const uint2*)(g_Th + (size_t)__float_as_int(e0.x) * 128 + lane * 4);
        uint2 u1 = *(const uint2*)(g_Th + (size_t)__float_as_int(e1.x) * 128 + lane * 4);
        uint2 u2 = *(const uint2*)(g_Th + (size_t)__float_as_int(e2.x) * 128 + lane * 4);
        uint2 u3 = *(const uint2*)(g_Th + (size_t)__float_as_int(e3.x) * 128 + lane * 4);
        acc4(ax, ay, az, aw, u0, e0.y);
        acc4(ax, ay, az, aw, u1, e1.y);
        acc4(ax, ay, az, aw, u2, e2.y);
        acc4(ax, ay, az, aw, u3, e3.y);
    }
    for (; i < end; i++) {
        float2 e0 = g_sw[i];
        uint2 u0 = *(const uint2*)(g_Th + (size_t)__float_as_int(e0.x) * 128 + lane * 4);
        acc4(ax, ay, az, aw, u0, e0.y);
    }
    float4 o = make_float4(ax, ay, az, aw);
    *(float4*)(buf(ysel) + (size_t)warp * 128 + lane * 4) = o;
}

// ---------------- pooling ----------------
__global__ void __launch_bounds__(128) pool_accum(int ysel, const void* __restrict__ batch, int n) {
    __shared__ int sb[256];
    int f  = threadIdx.x;
    int v0 = blockIdx.x * 256;
    for (int i = f; i < 256; i += 128) {
        int v = v0 + i;
        sb[i] = (v < n) ? batch_at(batch, v) : -1;
    }
    __syncthreads();
    const float* Y = buf(ysel);
    float acc = 0.f, ccnt = 0.f;
    int curg = -1;
    for (int i = 0; i < 256; i++) {
        int g = sb[i];
        if (g < 0) break;
        if (g != curg) {
            if (curg >= 0) {
                atomicAdd(&g_sums[curg * FD + f], acc);
                if (f == 0) atomicAdd(&g_cnt[curg], ccnt);
            }
            acc = 0.f; ccnt = 0.f; curg = g;
        }
        acc  += Y[(size_t)(v0 + i) * FD + f];
        ccnt += 1.f;
    }
    if (curg >= 0) {
        atomicAdd(&g_sums[curg * FD + f], acc);
        if (f == 0) atomicAdd(&g_cnt[curg], ccnt);
    }
}

// ---------------- finalize ----------------
__global__ void __launch_bounds__(128) finalize(
    const float* __restrict__ Wlin, const float* __restrict__ blin,
    float* __restrict__ out, int out_size)
{
    int g = blockIdx.x;
    int f = threadIdx.x;
    __shared__ float se[FD];
    float e = g_sums[g * FD + f] / fmaxf(g_cnt[g], 1.0f);
    se[f] = e;
    if (out_size >= NG * NC + NG * FD)
        out[NG * NC + g * FD + f] = e;
    __syncthreads();
    if (f < NC) {
        float s = blin[f];
#pragma unroll
        for (int k = 0; k < FD; k++)
            s = fmaf(se[k], Wlin[k * NC + f], s);
        out[g * NC + f] = s;
    }
}

// ---------------- launch ----------------
extern "C" void kernel_launch(void* const* d_in, const int* in_sizes, int n_in,
                              void* d_out, int out_size) {
    const float* x    = (const float*)d_in[0];
    const void*  ei   = d_in[1];
    const void*  batch= d_in[2];
    const float* W1   = (const float*)d_in[3];
    const float* b1   = (const float*)d_in[4];
    const float* W2   = (const float*)d_in[5];
    const float* b2   = (const float*)d_in[6];
    const float* W3   = (const float*)d_in[7];
    const float* b3   = (const float*)d_in[8];
    const float* Wlin = (const float*)d_in[9];
    const float* blin = (const float*)d_in[10];
    float* out = (float*)d_out;
    const int n = NN;

    const int gemm_grid = (NN + 63) / 64;
    const int agg_grid  = (NN * 32 + 255) / 256;

    detect_i64 <<<1, 256>>>((const int*)batch);        // 0
    zero_init  <<<(NN + 255) / 256, 256>>>();          // 1
    count_edges<<<(NE + 255) / 256, 256>>>(ei);        // 2
    gemm128    <<<gemm_grid, 256>>>(x, -1, 0, W1, n);  // 3  (layer-1 GEMM, CSR-independent)
    dinv_k     <<<(NN + 255) / 256, 256>>>();          // 4
    scan1      <<<SCAN_BLOCKS, 256>>>();               // 5
    scan2      <<<1, 128>>>();                         // 6
    scan3      <<<SCAN_BLOCKS, 256>>>();               // 7
    fill_csr   <<<(NE + 255) / 256, 256>>>(ei);        // 8

    aggregate  <<<agg_grid, 256>>>(1, b1);             // layer 1 aggregate -> HA
    gemm128    <<<gemm_grid, 256>>>(nullptr, 1, 1, W2, n);
    aggregate  <<<agg_grid, 256>>>(2, b2);             // -> HB
    gemm128    <<<gemm_grid, 256>>>(nullptr, 2, 1, W3, n);
    aggregate  <<<agg_grid, 256>>>(1, b3);             // -> HA

    pool_accum<<<(NN + 255) / 256, 128>>>(1, batch, n);
    finalize  <<<NG, 128>>>(Wlin, blin, out, out_size);
}

// round 4
// speedup vs baseline: 4.5121x; 1.4493x over previous
#include <cuda_runtime.h>
#include <cuda_fp16.h>

#define NN 100000
#define FD 128
#define NE 1600000
#define NG 64
#define NC 10
#define SCAN_CHUNK 1024
#define SCAN_BLOCKS ((NN + SCAN_CHUNK - 1) / SCAN_CHUNK)   // 98

// ---------------- scratch (device globals; no allocation) ----------------
__device__ __half  g_Xh[(size_t)NN * FD];  // GEMM input (half, relu applied for L2/3)
__device__ __half  g_Th[(size_t)NN * FD];  // GEMM output (half, gather source)
__device__ float   g_HA[(size_t)NN * FD];  // final layer activations (fp32, for pool)
__device__ __half  g_Wt[FD * FD];          // current layer W, transposed, half
__device__ float   g_dinv[NN];
__device__ int     g_cntN[NN];
__device__ int     g_rowptr[NN + 1];
__device__ int     g_pos[NN];
__device__ int     g_bsum[128];
__device__ float2  g_sw[NE];               // .x = src (bits), .y = edge weight
__device__ float   g_sums[NG * FD];
__device__ float   g_cnt [NG];
__device__ int     g_is64;

__device__ __forceinline__ int edge_src(const void* ei, int e) {
    return g_is64 ? (int)((const long long*)ei)[e] : ((const int*)ei)[e];
}
__device__ __forceinline__ int edge_dst(const void* ei, int e) {
    return g_is64 ? (int)((const long long*)ei)[(size_t)NE + e]
                  : ((const int*)ei)[(size_t)NE + e];
}
__device__ __forceinline__ int batch_at(const void* b, int v) {
    return g_is64 ? (int)((const long long*)b)[v] : ((const int*)b)[v];
}

// ---------------- dtype detection (batch sorted in [0,64)) ----------------
__global__ void detect_i64(const int* __restrict__ batch_words) {
    __shared__ int found;
    if (threadIdx.x == 0) found = 0;
    __syncthreads();
    int local = 0;
    for (int i = threadIdx.x; i < NN / 2; i += blockDim.x)
        if (batch_words[2 * i + 1] != 0) local = 1;
    if (local) atomicOr(&found, 1);
    __syncthreads();
    if (threadIdx.x == 0) g_is64 = (found == 0) ? 1 : 0;
}

// ---------------- zero init / degree ----------------
__global__ void zero_init() {
    int i = blockIdx.x * blockDim.x + threadIdx.x;
    if (i < NN) g_cntN[i] = 0;
    if (i < NG * FD) g_sums[i] = 0.0f;
    if (i < NG) g_cnt[i] = 0.0f;
}
__global__ void count_edges(const void* __restrict__ ei) {
    int e = blockIdx.x * blockDim.x + threadIdx.x;
    if (e < NE) atomicAdd(&g_cntN[edge_dst(ei, e)], 1);
}
__global__ void dinv_k() {
    int v = blockIdx.x * blockDim.x + threadIdx.x;
    if (v < NN) g_dinv[v] = rsqrtf((float)(g_cntN[v] + 1));
}

// ---------------- scan (3 phases) ----------------
__global__ void __launch_bounds__(256) scan1() {
    __shared__ int warp_tot[8];
    int base = blockIdx.x * SCAN_CHUNK + threadIdx.x * 4;
    int lane = threadIdx.x & 31, w = threadIdx.x >> 5;
    int v0 = (base + 0 < NN) ? g_cntN[base + 0] : 0;
    int v1 = (base + 1 < NN) ? g_cntN[base + 1] : 0;
    int v2 = (base + 2 < NN) ? g_cntN[base + 2] : 0;
    int v3 = (base + 3 < NN) ? g_cntN[base + 3] : 0;
    int tot = v0 + v1 + v2 + v3;
    int inc = tot;
#pragma unroll
    for (int o = 1; o < 32; o <<= 1) {
        int t = __shfl_up_sync(~0u, inc, o);
        if (lane >= o) inc += t;
    }
    if (lane == 31) warp_tot[w] = inc;
    __syncthreads();
    if (w == 0 && lane < 8) {
        int t = warp_tot[lane];
#pragma unroll
        for (int o = 1; o < 8; o <<= 1) {
            int u = __shfl_up_sync(0xffu, t, o);
            if (lane >= o) t += u;
        }
        warp_tot[lane] = t;
    }
    __syncthreads();
    int excl = ((w > 0) ? warp_tot[w - 1] : 0) + (inc - tot);
    if (base + 0 < NN) g_rowptr[base + 0] = excl;
    if (base + 1 < NN) g_rowptr[base + 1] = excl + v0;
    if (base + 2 < NN) g_rowptr[base + 2] = excl + v0 + v1;
    if (base + 3 < NN) g_rowptr[base + 3] = excl + v0 + v1 + v2;
    if (threadIdx.x == 255) g_bsum[blockIdx.x] = warp_tot[7];
}
__global__ void __launch_bounds__(128) scan2() {
    __shared__ int wt[4];
    int tid = threadIdx.x, lane = tid & 31, w = tid >> 5;
    int v = (tid < SCAN_BLOCKS) ? g_bsum[tid] : 0;
    int inc = v;
#pragma unroll
    for (int o = 1; o < 32; o <<= 1) {
        int t = __shfl_up_sync(~0u, inc, o);
        if (lane >= o) inc += t;
    }
    if (lane == 31) wt[w] = inc;
    __syncthreads();
    if (w == 0 && lane < 4) {
        int t = wt[lane];
#pragma unroll
        for (int o = 1; o < 4; o <<= 1) {
            int u = __shfl_up_sync(0xfu, t, o);
            if (lane >= o) t += u;
        }
        wt[lane] = t;
    }
    __syncthreads();
    int excl = ((w > 0) ? wt[w - 1] : 0) + (inc - v);
    if (tid < SCAN_BLOCKS) g_bsum[tid] = excl;
    if (tid == 0) g_rowptr[NN] = NE;
}
__global__ void __launch_bounds__(256) scan3() {
    int off = g_bsum[blockIdx.x];
    int base = blockIdx.x * SCAN_CHUNK + threadIdx.x * 4;
#pragma unroll
    for (int j = 0; j < 4; j++) {
        int idx = base + j;
        if (idx < NN) {
            int val = g_rowptr[idx] + off;
            g_rowptr[idx] = val;
            g_pos[idx] = val;
        }
    }
}
__global__ void fill_csr(const void* __restrict__ ei) {
    int e = blockIdx.x * blockDim.x + threadIdx.x;
    if (e >= NE) return;
    int s = edge_src(ei, e);
    int d = edge_dst(ei, e);
    int p = atomicAdd(&g_pos[d], 1);
    g_sw[p] = make_float2(__int_as_float(s), g_dinv[s] * g_dinv[d]);
}

// ---------------- converters ----------------
__global__ void convert_x(const float* __restrict__ x) {
    int i = blockIdx.x * blockDim.x + threadIdx.x;   // one per 8 elements
    if (i >= NN * FD / 8) return;
    const float4* src = (const float4*)x + i * 2;
    float4 f0 = src[0];
    float4 f1 = src[1];
    uint4 u;
    __half2 h;
    h = __floats2half2_rn(f0.x, f0.y); u.x = *(unsigned int*)&h;
    h = __floats2half2_rn(f0.z, f0.w); u.y = *(unsigned int*)&h;
    h = __floats2half2_rn(f1.x, f1.y); u.z = *(unsigned int*)&h;
    h = __floats2half2_rn(f1.z, f1.w); u.w = *(unsigned int*)&h;
    *((uint4*)g_Xh + i) = u;
}
// Wt[n][k] = half(W[k][n])
__global__ void convert_w(const float* __restrict__ W) {
    int i = blockIdx.x * blockDim.x + threadIdx.x;   // i = k*128+n (coalesced read)
    if (i >= FD * FD) return;
    int k = i >> 7, n = i & 127;
    g_Wt[n * FD + k] = __float2half_rn(W[i]);
}

// ---------------- tensor-core GEMM: Th = half(Xh @ W) ----------------
// block 256 thr (8 warps), tile M=128 N=128, K chunked by 64.
// warp grid 4x2 -> warp tile 32x64. mma.m16n8k16 f16->f32.
__global__ void __launch_bounds__(256) gemm_h(int nothing) {
    __shared__ __align__(16) __half As[128 * 72];
    __shared__ __align__(16) __half Bs[128 * 72];

    const int tid  = threadIdx.x;
    const int warp = tid >> 5;
    const int lane = tid & 31;
    const int wm = warp >> 1;       // 0..3
    const int wn = warp & 1;        // 0..1
    const int row0 = blockIdx.x * 128;
    const int gr = lane >> 2;       // 0..7
    const int ck = (lane & 3) * 2;  // 0,2,4,6

    float c[2][8][4];
#pragma unroll
    for (int mi = 0; mi < 2; mi++)
#pragma unroll
        for (int ni = 0; ni < 8; ni++)
#pragma unroll
            for (int q = 0; q < 4; q++) c[mi][ni][q] = 0.0f;

#pragma unroll
    for (int kc = 0; kc < 2; kc++) {
        // load A chunk [128 x 64]
#pragma unroll
        for (int it = 0; it < 4; it++) {
            int i = tid + it * 256;
            int r = i >> 3, kq = i & 7;
            uint4 v = make_uint4(0u, 0u, 0u, 0u);
            if (row0 + r < NN)
                v = *(const uint4*)(g_Xh + (size_t)(row0 + r) * FD + kc * 64 + kq * 8);
            *(uint4*)(As + r * 72 + kq * 8) = v;
        }
        // load B chunk: Bs[n][k] = Wt[n][kc*64 + k]
#pragma unroll
        for (int it = 0; it < 4; it++) {
            int i = tid + it * 256;
            int nr = i >> 3, kq = i & 7;
            *(uint4*)(Bs + nr * 72 + kq * 8) =
                *(const uint4*)(g_Wt + nr * FD + kc * 64 + kq * 8);
        }
        __syncthreads();

#pragma unroll
        for (int kk = 0; kk < 4; kk++) {
            int kb = kk * 16;
            unsigned int a[2][4];
#pragma unroll
            for (int mi = 0; mi < 2; mi++) {
                const __half* base = As + (wm * 32 + mi * 16 + gr) * 72 + kb + ck;
                a[mi][0] = *(const unsigned int*)(base);
                a[mi][1] = *(const unsigned int*)(base + 8 * 72);
                a[mi][2] = *(const unsigned int*)(base + 8);
                a[mi][3] = *(const unsigned int*)(base + 8 * 72 + 8);
            }
#pragma unroll
            for (int ni = 0; ni < 8; ni++) {
                const __half* bb = Bs + (wn * 64 + ni * 8 + gr) * 72 + kb + ck;
                unsigned int b0 = *(const unsigned int*)(bb);
                unsigned int b1 = *(const unsigned int*)(bb + 8);
#pragma unroll
                for (int mi = 0; mi < 2; mi++) {
                    asm volatile(
                        "mma.sync.aligned.m16n8k16.row.col.f32.f16.f16.f32 "
                        "{%0,%1,%2,%3}, {%4,%5,%6,%7}, {%8,%9}, {%0,%1,%2,%3};"
                        : "+f"(c[mi][ni][0]), "+f"(c[mi][ni][1]),
                          "+f"(c[mi][ni][2]), "+f"(c[mi][ni][3])
                        : "r"(a[mi][0]), "r"(a[mi][1]), "r"(a[mi][2]), "r"(a[mi][3]),
                          "r"(b0), "r"(b1));
                }
            }
        }
        __syncthreads();
    }

    // epilogue: store half to g_Th
    const int cc = (lane & 3) * 2;
#pragma unroll
    for (int mi = 0; mi < 2; mi++) {
#pragma unroll
        for (int ni = 0; ni < 8; ni++) {
            int row = row0 + wm * 32 + mi * 16 + gr;
            int col = wn * 64 + ni * 8 + cc;
            if (row < NN) {
                __half2 h0 = __floats2half2_rn(c[mi][ni][0], c[mi][ni][1]);
                *(unsigned int*)(g_Th + (size_t)row * FD + col) = *(unsigned int*)&h0;
            }
            if (row + 8 < NN) {
                __half2 h1 = __floats2half2_rn(c[mi][ni][2], c[mi][ni][3]);
                *(unsigned int*)(g_Th + (size_t)(row + 8) * FD + col) = *(unsigned int*)&h1;
            }
        }
    }
}

// ---------------- fused aggregation (half gathers, fp32 accum) ----------------
__device__ __forceinline__ void acc4(float& ax, float& ay, float& az, float& aw,
                                     uint2 u, float wgt) {
    __half2 h0 = *reinterpret_cast<__half2*>(&u.x);
    __half2 h1 = *reinterpret_cast<__half2*>(&u.y);
    float2 f0 = __half22float2(h0);
    float2 f1 = __half22float2(h1);
    ax = fmaf(f0.x, wgt, ax); ay = fmaf(f0.y, wgt, ay);
    az = fmaf(f1.x, wgt, az); aw = fmaf(f1.y, wgt, aw);
}

// mode 0: write relu(acc) as half into g_Xh (mid layers)
// mode 1: write acc as fp32 into g_HA (final layer)
__global__ void __launch_bounds__(256) aggregate(int mode, const float* __restrict__ bias) {
    int warp = (blockIdx.x * 256 + threadIdx.x) >> 5;
    if (warp >= NN) return;
    int lane = threadIdx.x & 31;
    int beg = g_rowptr[warp], end = g_rowptr[warp + 1];
    float di = g_dinv[warp];
    float cnorm = di * di;
    float4 bb = *(const float4*)(bias + lane * 4);
    float ax = bb.x, ay = bb.y, az = bb.z, aw = bb.w;
    {
        uint2 u = *(const uint2*)(g_Th + (size_t)warp * FD + lane * 4);
        acc4(ax, ay, az, aw, u, cnorm);
    }

    int i = beg;
    for (; i + 4 <= end; i += 4) {
        float2 e0 = g_sw[i + 0];
        float2 e1 = g_sw[i + 1];
        float2 e2 = g_sw[i + 2];
        float2 e3 = g_sw[i + 3];
        uint2 u0 = *(const uint2*)(g_Th + (size_t)__float_as_int(e0.x) * FD + lane * 4);
        uint2 u1 = *(const uint2*)(g_Th + (size_t)__float_as_int(e1.x) * FD + lane * 4);
        uint2 u2 = *(const uint2*)(g_Th + (size_t)__float_as_int(e2.x) * FD + lane * 4);
        uint2 u3 = *(const uint2*)(g_Th + (size_t)__float_as_int(e3.x) * FD + lane * 4);
        acc4(ax, ay, az, aw, u0, e0.y);
        acc4(ax, ay, az, aw, u1, e1.y);
        acc4(ax, ay, az, aw, u2, e2.y);
        acc4(ax, ay, az, aw, u3, e3.y);
    }
    for (; i < end; i++) {
        float2 e0 = g_sw[i];
        uint2 u0 = *(const uint2*)(g_Th + (size_t)__float_as_int(e0.x) * FD + lane * 4);
        acc4(ax, ay, az, aw, u0, e0.y);
    }

    if (mode == 0) {
        __half2 h0 = __floats2half2_rn(fmaxf(ax, 0.f), fmaxf(ay, 0.f));
        __half2 h1 = __floats2half2_rn(fmaxf(az, 0.f), fmaxf(aw, 0.f));
        uint2 u;
        u.x = *(unsigned int*)&h0;
        u.y = *(unsigned int*)&h1;
        *(uint2*)(g_Xh + (size_t)warp * FD + lane * 4) = u;
    } else {
        float4 o = make_float4(ax, ay, az, aw);
        *(float4*)(g_HA + (size_t)warp * FD + lane * 4) = o;
    }
}

// ---------------- pooling ----------------
__global__ void __launch_bounds__(128) pool_accum(const void* __restrict__ batch, int n) {
    __shared__ int sb[256];
    int f  = threadIdx.x;
    int v0 = blockIdx.x * 256;
    for (int i = f; i < 256; i += 128) {
        int v = v0 + i;
        sb[i] = (v < n) ? batch_at(batch, v) : -1;
    }
    __syncthreads();
    float acc = 0.f, ccnt = 0.f;
    int curg = -1;
    for (int i = 0; i < 256; i++) {
        int g = sb[i];
        if (g < 0) break;
        if (g != curg) {
            if (curg >= 0) {
                atomicAdd(&g_sums[curg * FD + f], acc);
                if (f == 0) atomicAdd(&g_cnt[curg], ccnt);
            }
            acc = 0.f; ccnt = 0.f; curg = g;
        }
        acc  += g_HA[(size_t)(v0 + i) * FD + f];
        ccnt += 1.f;
    }
    if (curg >= 0) {
        atomicAdd(&g_sums[curg * FD + f], acc);
        if (f == 0) atomicAdd(&g_cnt[curg], ccnt);
    }
}

// ---------------- finalize ----------------
__global__ void __launch_bounds__(128) finalize(
    const float* __restrict__ Wlin, const float* __restrict__ blin,
    float* __restrict__ out, int out_size)
{
    int g = blockIdx.x;
    int f = threadIdx.x;
    __shared__ float se[FD];
    float e = g_sums[g * FD + f] / fmaxf(g_cnt[g], 1.0f);
    se[f] = e;
    if (out_size >= NG * NC + NG * FD)
        out[NG * NC + g * FD + f] = e;
    __syncthreads();
    if (f < NC) {
        float s = blin[f];
#pragma unroll
        for (int k = 0; k < FD; k++)
            s = fmaf(se[k], Wlin[k * NC + f], s);
        out[g * NC + f] = s;
    }
}

// ---------------- launch ----------------
extern "C" void kernel_launch(void* const* d_in, const int* in_sizes, int n_in,
                              void* d_out, int out_size) {
    const float* x    = (const float*)d_in[0];
    const void*  ei   = d_in[1];
    const void*  batch= d_in[2];
    const float* W1   = (const float*)d_in[3];
    const float* b1   = (const float*)d_in[4];
    const float* W2   = (const float*)d_in[5];
    const float* b2   = (const float*)d_in[6];
    const float* W3   = (const float*)d_in[7];
    const float* b3   = (const float*)d_in[8];
    const float* Wlin = (const float*)d_in[9];
    const float* blin = (const float*)d_in[10];
    float* out = (float*)d_out;
    const int n = NN;

    const int gemm_grid = (NN + 127) / 128;
    const int agg_grid  = (NN * 32 + 255) / 256;

    detect_i64 <<<1, 256>>>((const int*)batch);
    zero_init  <<<(NN + 255) / 256, 256>>>();
    count_edges<<<(NE + 255) / 256, 256>>>(ei);
    convert_x  <<<(NN * FD / 8 + 255) / 256, 256>>>(x);
    convert_w  <<<(FD * FD + 255) / 256, 256>>>(W1);
    gemm_h     <<<gemm_grid, 256>>>(0);                 // L1 GEMM (CSR-independent)
    dinv_k     <<<(NN + 255) / 256, 256>>>();
    scan1      <<<SCAN_BLOCKS, 256>>>();
    scan2      <<<1, 128>>>();
    scan3      <<<SCAN_BLOCKS, 256>>>();
    fill_csr   <<<(NE + 255) / 256, 256>>>(ei);

    aggregate  <<<agg_grid, 256>>>(0, b1);              // -> relu half Xh
    convert_w  <<<(FD * FD + 255) / 256, 256>>>(W2);
    gemm_h     <<<gemm_grid, 256>>>(0);
    aggregate  <<<agg_grid, 256>>>(0, b2);              // -> relu half Xh
    convert_w  <<<(FD * FD + 255) / 256, 256>>>(W3);
    gemm_h     <<<gemm_grid, 256>>>(0);
    aggregate  <<<agg_grid, 256>>>(1, b3);              // -> fp32 HA

    pool_accum<<<(NN + 255) / 256, 128>>>(batch, n);
    finalize  <<<NG, 128>>>(Wlin, blin, out, out_size);
}

// round 5
// speedup vs baseline: 4.8957x; 1.0850x over previous
#include <cuda_runtime.h>
#include <cuda_fp16.h>

#define NN 100000
#define FD 128
#define NE 1600000
#define NG 64
#define NC 10
#define SCAN_CHUNK 1024
#define SCAN_BLOCKS ((NN + SCAN_CHUNK - 1) / SCAN_CHUNK)   // 98

// ---------------- scratch ----------------
__device__ __half  g_Xh[(size_t)NN * FD];  // activations (half)
__device__ __half  g_Th[(size_t)NN * FD];  // GEMM output (half, gather source)
__device__ __half  g_Wt[3 * FD * FD];      // all W, transposed, half
__device__ float   g_dinv[NN];
__device__ int     g_cntN[NN];
__device__ int     g_rowptr[NN + 1];
__device__ int     g_pos[NN];
__device__ int     g_bsum[128];
__device__ float2  g_sw[NE];               // .x = src (bits), .y = edge weight
__device__ float   g_sums[NG * FD];
__device__ float   g_cnt [NG];
__device__ int     g_is64;

__device__ __forceinline__ int edge_src(const void* ei, int e) {
    return g_is64 ? (int)((const long long*)ei)[e] : ((const int*)ei)[e];
}
__device__ __forceinline__ int edge_dst(const void* ei, int e) {
    return g_is64 ? (int)((const long long*)ei)[(size_t)NE + e]
                  : ((const int*)ei)[(size_t)NE + e];
}
__device__ __forceinline__ int batch_at(const void* b, int v) {
    return g_is64 ? (int)((const long long*)b)[v] : ((const int*)b)[v];
}

// ---------------- dtype detection ----------------
__global__ void detect_i64(const int* __restrict__ batch_words) {
    __shared__ int found;
    if (threadIdx.x == 0) found = 0;
    __syncthreads();
    int local = 0;
    for (int i = threadIdx.x; i < NN / 2; i += blockDim.x)
        if (batch_words[2 * i + 1] != 0) local = 1;
    if (local) atomicOr(&found, 1);
    __syncthreads();
    if (threadIdx.x == 0) g_is64 = (found == 0) ? 1 : 0;
}

// ---------------- zero init / degree ----------------
__global__ void zero_init() {
    int i = blockIdx.x * blockDim.x + threadIdx.x;
    if (i < NN) g_cntN[i] = 0;
    if (i < NG * FD) g_sums[i] = 0.0f;
    if (i < NG) g_cnt[i] = 0.0f;
}
__global__ void count_edges(const void* __restrict__ ei) {
    int e = blockIdx.x * blockDim.x + threadIdx.x;
    if (e < NE) atomicAdd(&g_cntN[edge_dst(ei, e)], 1);
}
__global__ void dinv_k() {
    int v = blockIdx.x * blockDim.x + threadIdx.x;
    if (v < NN) g_dinv[v] = rsqrtf((float)(g_cntN[v] + 1));
}

// ---------------- scan (3 phases) ----------------
__global__ void __launch_bounds__(256) scan1() {
    __shared__ int warp_tot[8];
    int base = blockIdx.x * SCAN_CHUNK + threadIdx.x * 4;
    int lane = threadIdx.x & 31, w = threadIdx.x >> 5;
    int v0 = (base + 0 < NN) ? g_cntN[base + 0] : 0;
    int v1 = (base + 1 < NN) ? g_cntN[base + 1] : 0;
    int v2 = (base + 2 < NN) ? g_cntN[base + 2] : 0;
    int v3 = (base + 3 < NN) ? g_cntN[base + 3] : 0;
    int tot = v0 + v1 + v2 + v3;
    int inc = tot;
#pragma unroll
    for (int o = 1; o < 32; o <<= 1) {
        int t = __shfl_up_sync(~0u, inc, o);
        if (lane >= o) inc += t;
    }
    if (lane == 31) warp_tot[w] = inc;
    __syncthreads();
    if (w == 0 && lane < 8) {
        int t = warp_tot[lane];
#pragma unroll
        for (int o = 1; o < 8; o <<= 1) {
            int u = __shfl_up_sync(0xffu, t, o);
            if (lane >= o) t += u;
        }
        warp_tot[lane] = t;
    }
    __syncthreads();
    int excl = ((w > 0) ? warp_tot[w - 1] : 0) + (inc - tot);
    if (base + 0 < NN) g_rowptr[base + 0] = excl;
    if (base + 1 < NN) g_rowptr[base + 1] = excl + v0;
    if (base + 2 < NN) g_rowptr[base + 2] = excl + v0 + v1;
    if (base + 3 < NN) g_rowptr[base + 3] = excl + v0 + v1 + v2;
    if (threadIdx.x == 255) g_bsum[blockIdx.x] = warp_tot[7];
}
__global__ void __launch_bounds__(128) scan2() {
    __shared__ int wt[4];
    int tid = threadIdx.x, lane = tid & 31, w = tid >> 5;
    int v = (tid < SCAN_BLOCKS) ? g_bsum[tid] : 0;
    int inc = v;
#pragma unroll
    for (int o = 1; o < 32; o <<= 1) {
        int t = __shfl_up_sync(~0u, inc, o);
        if (lane >= o) inc += t;
    }
    if (lane == 31) wt[w] = inc;
    __syncthreads();
    if (w == 0 && lane < 4) {
        int t = wt[lane];
#pragma unroll
        for (int o = 1; o < 4; o <<= 1) {
            int u = __shfl_up_sync(0xfu, t, o);
            if (lane >= o) t += u;
        }
        wt[lane] = t;
    }
    __syncthreads();
    int excl = ((w > 0) ? wt[w - 1] : 0) + (inc - v);
    if (tid < SCAN_BLOCKS) g_bsum[tid] = excl;
    if (tid == 0) g_rowptr[NN] = NE;
}
__global__ void __launch_bounds__(256) scan3() {
    int off = g_bsum[blockIdx.x];
    int base = blockIdx.x * SCAN_CHUNK + threadIdx.x * 4;
#pragma unroll
    for (int j = 0; j < 4; j++) {
        int idx = base + j;
        if (idx < NN) {
            int val = g_rowptr[idx] + off;
            g_rowptr[idx] = val;
            g_pos[idx] = val;
        }
    }
}
__global__ void fill_csr(const void* __restrict__ ei) {
    int e = blockIdx.x * blockDim.x + threadIdx.x;
    if (e >= NE) return;
    int s = edge_src(ei, e);
    int d = edge_dst(ei, e);
    int p = atomicAdd(&g_pos[d], 1);
    g_sw[p] = make_float2(__int_as_float(s), g_dinv[s] * g_dinv[d]);
}

// ---------------- weight conversion: Wt[l][n][k] = half(W_l[k][n]) ----------------
__global__ void convert_w3(const float* __restrict__ W1,
                           const float* __restrict__ W2,
                           const float* __restrict__ W3) {
    int i = blockIdx.x * blockDim.x + threadIdx.x;
    if (i >= 3 * FD * FD) return;
    int l = i / (FD * FD);
    int j = i % (FD * FD);
    const float* W = (l == 0) ? W1 : (l == 1) ? W2 : W3;
    int k = j >> 7, n = j & 127;
    g_Wt[l * FD * FD + n * FD + k] = __float2half_rn(W[j]);
}

// ---------------- tensor-core GEMM: Th = half(A @ W) ----------------
// A = Xf (fp32, first layer) or g_Xh (half). Tile 128x128, K chunk 64.
__global__ void __launch_bounds__(256) gemm_h(const float* __restrict__ Xf, int wsel) {
    __shared__ __align__(16) __half As[128 * 72];
    __shared__ __align__(16) __half Bs[128 * 72];

    const int tid  = threadIdx.x;
    const int warp = tid >> 5;
    const int lane = tid & 31;
    const int wm = warp >> 1;       // 0..3
    const int wn = warp & 1;        // 0..1
    const int row0 = blockIdx.x * 128;
    const int gr = lane >> 2;       // 0..7
    const int ck = (lane & 3) * 2;  // 0,2,4,6
    const __half* Wt = g_Wt + wsel * FD * FD;

    float c[2][8][4];
#pragma unroll
    for (int mi = 0; mi < 2; mi++)
#pragma unroll
        for (int ni = 0; ni < 8; ni++)
#pragma unroll
            for (int q = 0; q < 4; q++) c[mi][ni][q] = 0.0f;

#pragma unroll
    for (int kc = 0; kc < 2; kc++) {
        // load A chunk [128 x 64]
        if (Xf != nullptr) {
#pragma unroll
            for (int it = 0; it < 8; it++) {
                int i = tid + it * 256;          // float4 slot, 0..2047
                int r = i >> 4, c4 = i & 15;
                float4 v = make_float4(0.f, 0.f, 0.f, 0.f);
                if (row0 + r < NN)
                    v = *(const float4*)(Xf + (size_t)(row0 + r) * FD + kc * 64 + c4 * 4);
                __half2 h0 = __floats2half2_rn(v.x, v.y);
                __half2 h1 = __floats2half2_rn(v.z, v.w);
                uint2 u;
                u.x = *(unsigned int*)&h0;
                u.y = *(unsigned int*)&h1;
                *(uint2*)(As + r * 72 + c4 * 4) = u;
            }
        } else {
#pragma unroll
            for (int it = 0; it < 4; it++) {
                int i = tid + it * 256;
                int r = i >> 3, kq = i & 7;
                uint4 v = make_uint4(0u, 0u, 0u, 0u);
                if (row0 + r < NN)
                    v = *(const uint4*)(g_Xh + (size_t)(row0 + r) * FD + kc * 64 + kq * 8);
                *(uint4*)(As + r * 72 + kq * 8) = v;
            }
        }
        // load B chunk: Bs[n][k] = Wt[n][kc*64 + k]
#pragma unroll
        for (int it = 0; it < 4; it++) {
            int i = tid + it * 256;
            int nr = i >> 3, kq = i & 7;
            *(uint4*)(Bs + nr * 72 + kq * 8) =
                *(const uint4*)(Wt + nr * FD + kc * 64 + kq * 8);
        }
        __syncthreads();

#pragma unroll
        for (int kk = 0; kk < 4; kk++) {
            int kb = kk * 16;
            unsigned int a[2][4];
#pragma unroll
            for (int mi = 0; mi < 2; mi++) {
                const __half* base = As + (wm * 32 + mi * 16 + gr) * 72 + kb + ck;
                a[mi][0] = *(const unsigned int*)(base);
                a[mi][1] = *(const unsigned int*)(base + 8 * 72);
                a[mi][2] = *(const unsigned int*)(base + 8);
                a[mi][3] = *(const unsigned int*)(base + 8 * 72 + 8);
            }
#pragma unroll
            for (int ni = 0; ni < 8; ni++) {
                const __half* bb = Bs + (wn * 64 + ni * 8 + gr) * 72 + kb + ck;
                unsigned int b0 = *(const unsigned int*)(bb);
                unsigned int b1 = *(const unsigned int*)(bb + 8);
#pragma unroll
                for (int mi = 0; mi < 2; mi++) {
                    asm volatile(
                        "mma.sync.aligned.m16n8k16.row.col.f32.f16.f16.f32 "
                        "{%0,%1,%2,%3}, {%4,%5,%6,%7}, {%8,%9}, {%0,%1,%2,%3};"
                        : "+f"(c[mi][ni][0]), "+f"(c[mi][ni][1]),
                          "+f"(c[mi][ni][2]), "+f"(c[mi][ni][3])
                        : "r"(a[mi][0]), "r"(a[mi][1]), "r"(a[mi][2]), "r"(a[mi][3]),
                          "r"(b0), "r"(b1));
                }
            }
        }
        __syncthreads();
    }

    const int cc = (lane & 3) * 2;
#pragma unroll
    for (int mi = 0; mi < 2; mi++) {
#pragma unroll
        for (int ni = 0; ni < 8; ni++) {
            int row = row0 + wm * 32 + mi * 16 + gr;
            int col = wn * 64 + ni * 8 + cc;
            if (row < NN) {
                __half2 h0 = __floats2half2_rn(c[mi][ni][0], c[mi][ni][1]);
                *(unsigned int*)(g_Th + (size_t)row * FD + col) = *(unsigned int*)&h0;
            }
            if (row + 8 < NN) {
                __half2 h1 = __floats2half2_rn(c[mi][ni][2], c[mi][ni][3]);
                *(unsigned int*)(g_Th + (size_t)(row + 8) * FD + col) = *(unsigned int*)&h1;
            }
        }
    }
}

// ---------------- fused aggregation: half-warp per node ----------------
// lane ln (0..15) handles 8 features via uint4 gathers; fp32 accum.
__device__ __forceinline__ void acc8(float* a, uint4 u, float w) {
    __half2 h; float2 f;
    h = *(__half2*)&u.x; f = __half22float2(h);
    a[0] = fmaf(f.x, w, a[0]); a[1] = fmaf(f.y, w, a[1]);
    h = *(__half2*)&u.y; f = __half22float2(h);
    a[2] = fmaf(f.x, w, a[2]); a[3] = fmaf(f.y, w, a[3]);
    h = *(__half2*)&u.z; f = __half22float2(h);
    a[4] = fmaf(f.x, w, a[4]); a[5] = fmaf(f.y, w, a[5]);
    h = *(__half2*)&u.w; f = __half22float2(h);
    a[6] = fmaf(f.x, w, a[6]); a[7] = fmaf(f.y, w, a[7]);
}

// mode 0: write relu(acc) half -> g_Xh; mode 1: write acc half (no relu) -> g_Xh
__global__ void __launch_bounds__(256) aggregate(int mode, const float* __restrict__ bias) {
    int gwarp = (blockIdx.x * 256 + threadIdx.x) >> 5;
    int lane = threadIdx.x & 31;
    int node = gwarp * 2 + (lane >> 4);
    int ln = lane & 15;
    if (node >= NN) return;
    int beg = g_rowptr[node], end = g_rowptr[node + 1];
    float di = g_dinv[node];
    float cnorm = di * di;

    float a[8];
    {
        float4 b0 = *(const float4*)(bias + ln * 8);
        float4 b1 = *(const float4*)(bias + ln * 8 + 4);
        a[0] = b0.x; a[1] = b0.y; a[2] = b0.z; a[3] = b0.w;
        a[4] = b1.x; a[5] = b1.y; a[6] = b1.z; a[7] = b1.w;
    }
    {
        uint4 u = *(const uint4*)(g_Th + (size_t)node * FD + ln * 8);
        acc8(a, u, cnorm);
    }

    int i = beg;
    for (; i + 4 <= end; i += 4) {
        float2 e0 = g_sw[i + 0];
        float2 e1 = g_sw[i + 1];
        float2 e2 = g_sw[i + 2];
        float2 e3 = g_sw[i + 3];
        uint4 u0 = *(const uint4*)(g_Th + (size_t)__float_as_int(e0.x) * FD + ln * 8);
        uint4 u1 = *(const uint4*)(g_Th + (size_t)__float_as_int(e1.x) * FD + ln * 8);
        uint4 u2 = *(const uint4*)(g_Th + (size_t)__float_as_int(e2.x) * FD + ln * 8);
        uint4 u3 = *(const uint4*)(g_Th + (size_t)__float_as_int(e3.x) * FD + ln * 8);
        acc8(a, u0, e0.y);
        acc8(a, u1, e1.y);
        acc8(a, u2, e2.y);
        acc8(a, u3, e3.y);
    }
    for (; i < end; i++) {
        float2 e0 = g_sw[i];
        uint4 u0 = *(const uint4*)(g_Th + (size_t)__float_as_int(e0.x) * FD + ln * 8);
        acc8(a, u0, e0.y);
    }

    if (mode == 0) {
#pragma unroll
        for (int q = 0; q < 8; q++) a[q] = fmaxf(a[q], 0.f);
    }
    __half2 h0 = __floats2half2_rn(a[0], a[1]);
    __half2 h1 = __floats2half2_rn(a[2], a[3]);
    __half2 h2 = __floats2half2_rn(a[4], a[5]);
    __half2 h3 = __floats2half2_rn(a[6], a[7]);
    uint4 u;
    u.x = *(unsigned int*)&h0;
    u.y = *(unsigned int*)&h1;
    u.z = *(unsigned int*)&h2;
    u.w = *(unsigned int*)&h3;
    *(uint4*)(g_Xh + (size_t)node * FD + ln * 8) = u;
}

// ---------------- pooling (reads half activations) ----------------
__global__ void __launch_bounds__(128) pool_accum(const void* __restrict__ batch, int n) {
    __shared__ int sb[256];
    int f  = threadIdx.x;
    int v0 = blockIdx.x * 256;
    for (int i = f; i < 256; i += 128) {
        int v = v0 + i;
        sb[i] = (v < n) ? batch_at(batch, v) : -1;
    }
    __syncthreads();
    float acc = 0.f, ccnt = 0.f;
    int curg = -1;
    for (int i = 0; i < 256; i++) {
        int g = sb[i];
        if (g < 0) break;
        if (g != curg) {
            if (curg >= 0) {
                atomicAdd(&g_sums[curg * FD + f], acc);
                if (f == 0) atomicAdd(&g_cnt[curg], ccnt);
            }
            acc = 0.f; ccnt = 0.f; curg = g;
        }
        acc  += __half2float(g_Xh[(size_t)(v0 + i) * FD + f]);
        ccnt += 1.f;
    }
    if (curg >= 0) {
        atomicAdd(&g_sums[curg * FD + f], acc);
        if (f == 0) atomicAdd(&g_cnt[curg], ccnt);
    }
}

// ---------------- finalize ----------------
__global__ void __launch_bounds__(128) finalize(
    const float* __restrict__ Wlin, const float* __restrict__ blin,
    float* __restrict__ out, int out_size)
{
    int g = blockIdx.x;
    int f = threadIdx.x;
    __shared__ float se[FD];
    float e = g_sums[g * FD + f] / fmaxf(g_cnt[g], 1.0f);
    se[f] = e;
    if (out_size >= NG * NC + NG * FD)
        out[NG * NC + g * FD + f] = e;
    __syncthreads();
    if (f < NC) {
        float s = blin[f];
#pragma unroll
        for (int k = 0; k < FD; k++)
            s = fmaf(se[k], Wlin[k * NC + f], s);
        out[g * NC + f] = s;
    }
}

// ---------------- launch ----------------
extern "C" void kernel_launch(void* const* d_in, const int* in_sizes, int n_in,
                              void* d_out, int out_size) {
    const float* x    = (const float*)d_in[0];
    const void*  ei   = d_in[1];
    const void*  batch= d_in[2];
    const float* W1   = (const float*)d_in[3];
    const float* b1   = (const float*)d_in[4];
    const float* W2   = (const float*)d_in[5];
    const float* b2   = (const float*)d_in[6];
    const float* W3   = (const float*)d_in[7];
    const float* b3   = (const float*)d_in[8];
    const float* Wlin = (const float*)d_in[9];
    const float* blin = (const float*)d_in[10];
    float* out = (float*)d_out;
    const int n = NN;

    const int gemm_grid = (NN + 127) / 128;
    const int agg_grid  = (NN * 16 + 255) / 256;

    detect_i64 <<<1, 256>>>((const int*)batch);                 // 0
    zero_init  <<<(NN + 255) / 256, 256>>>();                   // 1
    convert_w3 <<<(3 * FD * FD + 255) / 256, 256>>>(W1, W2, W3);// 2
    gemm_h     <<<gemm_grid, 256>>>(x, 0);                      // 3 (profiled)
    count_edges<<<(NE + 255) / 256, 256>>>(ei);                 // 4
    dinv_k     <<<(NN + 255) / 256, 256>>>();                   // 5
    scan1      <<<SCAN_BLOCKS, 256>>>();
    scan2      <<<1, 128>>>();
    scan3      <<<SCAN_BLOCKS, 256>>>();
    fill_csr   <<<(NE + 255) / 256, 256>>>(ei);

    aggregate  <<<agg_grid, 256>>>(0, b1);     // -> relu half Xh
    gemm_h     <<<gemm_grid, 256>>>(nullptr, 1);
    aggregate  <<<agg_grid, 256>>>(0, b2);     // -> relu half Xh
    gemm_h     <<<gemm_grid, 256>>>(nullptr, 2);
    aggregate  <<<agg_grid, 256>>>(1, b3);     // -> half Xh (no relu)

    pool_accum<<<(NN + 255) / 256, 128>>>(batch, n);
    finalize  <<<NG, 128>>>(Wlin, blin, out, out_size);
}

// round 6
// speedup vs baseline: 5.2282x; 1.0679x over previous
#include <cuda_runtime.h>
#include <cuda_fp16.h>

#define NN 100000
#define FD 128
#define NE 1600000
#define NG 64
#define NC 10
#define SCAN_CHUNK 1024
#define SCAN_BLOCKS ((NN + SCAN_CHUNK - 1) / SCAN_CHUNK)   // 98

// ---------------- scratch ----------------
__device__ __half  g_Xh[(size_t)NN * FD];  // activations (half)
__device__ __half  g_Th[(size_t)NN * FD];  // GEMM output (half, gather source)
__device__ __half  g_Wt[3 * FD * FD];      // all W, transposed, half
__device__ float   g_dinv[NN];
__device__ int     g_cntN[NN];
__device__ int     g_rowptr[NN + 1];
__device__ int     g_pos[NN];
__device__ int     g_bsum[128];
__device__ float2  g_sw[NE];               // .x = src (bits), .y = edge weight
__device__ float   g_sums[NG * FD];
__device__ float   g_cnt [NG];
__device__ int     g_is64;

__device__ __forceinline__ int edge_src(const void* ei, int e) {
    return g_is64 ? (int)((const long long*)ei)[e] : ((const int*)ei)[e];
}
__device__ __forceinline__ int edge_dst(const void* ei, int e) {
    return g_is64 ? (int)((const long long*)ei)[(size_t)NE + e]
                  : ((const int*)ei)[(size_t)NE + e];
}
__device__ __forceinline__ int batch_at(const void* b, int v) {
    return g_is64 ? (int)((const long long*)b)[v] : ((const int*)b)[v];
}

// ---------------- dtype detection ----------------
__global__ void detect_i64(const int* __restrict__ batch_words) {
    __shared__ int found;
    if (threadIdx.x == 0) found = 0;
    __syncthreads();
    int local = 0;
    for (int i = threadIdx.x; i < NN / 2; i += blockDim.x)
        if (batch_words[2 * i + 1] != 0) local = 1;
    if (local) atomicOr(&found, 1);
    __syncthreads();
    if (threadIdx.x == 0) g_is64 = (found == 0) ? 1 : 0;
}

// ---------------- zero init / degree ----------------
__global__ void zero_init() {
    int i = blockIdx.x * blockDim.x + threadIdx.x;
    if (i < NN) g_cntN[i] = 0;
    if (i < NG * FD) g_sums[i] = 0.0f;
    if (i < NG) g_cnt[i] = 0.0f;
}
__global__ void count_edges(const void* __restrict__ ei) {
    int e = blockIdx.x * blockDim.x + threadIdx.x;
    if (e < NE) atomicAdd(&g_cntN[edge_dst(ei, e)], 1);
}
__global__ void dinv_k() {
    int v = blockIdx.x * blockDim.x + threadIdx.x;
    if (v < NN) g_dinv[v] = rsqrtf((float)(g_cntN[v] + 1));
}

// ---------------- scan (3 phases) ----------------
__global__ void __launch_bounds__(256) scan1() {
    __shared__ int warp_tot[8];
    int base = blockIdx.x * SCAN_CHUNK + threadIdx.x * 4;
    int lane = threadIdx.x & 31, w = threadIdx.x >> 5;
    int v0 = (base + 0 < NN) ? g_cntN[base + 0] : 0;
    int v1 = (base + 1 < NN) ? g_cntN[base + 1] : 0;
    int v2 = (base + 2 < NN) ? g_cntN[base + 2] : 0;
    int v3 = (base + 3 < NN) ? g_cntN[base + 3] : 0;
    int tot = v0 + v1 + v2 + v3;
    int inc = tot;
#pragma unroll
    for (int o = 1; o < 32; o <<= 1) {
        int t = __shfl_up_sync(~0u, inc, o);
        if (lane >= o) inc += t;
    }
    if (lane == 31) warp_tot[w] = inc;
    __syncthreads();
    if (w == 0 && lane < 8) {
        int t = warp_tot[lane];
#pragma unroll
        for (int o = 1; o < 8; o <<= 1) {
            int u = __shfl_up_sync(0xffu, t, o);
            if (lane >= o) t += u;
        }
        warp_tot[lane] = t;
    }
    __syncthreads();
    int excl = ((w > 0) ? warp_tot[w - 1] : 0) + (inc - tot);
    if (base + 0 < NN) g_rowptr[base + 0] = excl;
    if (base + 1 < NN) g_rowptr[base + 1] = excl + v0;
    if (base + 2 < NN) g_rowptr[base + 2] = excl + v0 + v1;
    if (base + 3 < NN) g_rowptr[base + 3] = excl + v0 + v1 + v2;
    if (threadIdx.x == 255) g_bsum[blockIdx.x] = warp_tot[7];
}
__global__ void __launch_bounds__(128) scan2() {
    __shared__ int wt[4];
    int tid = threadIdx.x, lane = tid & 31, w = tid >> 5;
    int v = (tid < SCAN_BLOCKS) ? g_bsum[tid] : 0;
    int inc = v;
#pragma unroll
    for (int o = 1; o < 32; o <<= 1) {
        int t = __shfl_up_sync(~0u, inc, o);
        if (lane >= o) inc += t;
    }
    if (lane == 31) wt[w] = inc;
    __syncthreads();
    if (w == 0 && lane < 4) {
        int t = wt[lane];
#pragma unroll
        for (int o = 1; o < 4; o <<= 1) {
            int u = __shfl_up_sync(0xfu, t, o);
            if (lane >= o) t += u;
        }
        wt[lane] = t;
    }
    __syncthreads();
    int excl = ((w > 0) ? wt[w - 1] : 0) + (inc - v);
    if (tid < SCAN_BLOCKS) g_bsum[tid] = excl;
    if (tid == 0) g_rowptr[NN] = NE;
}
__global__ void __launch_bounds__(256) scan3() {
    int off = g_bsum[blockIdx.x];
    int base = blockIdx.x * SCAN_CHUNK + threadIdx.x * 4;
#pragma unroll
    for (int j = 0; j < 4; j++) {
        int idx = base + j;
        if (idx < NN) {
            int val = g_rowptr[idx] + off;
            g_rowptr[idx] = val;
            g_pos[idx] = val;
        }
    }
}
__global__ void fill_csr(const void* __restrict__ ei) {
    int e = blockIdx.x * blockDim.x + threadIdx.x;
    if (e >= NE) return;
    int s = edge_src(ei, e);
    int d = edge_dst(ei, e);
    int p = atomicAdd(&g_pos[d], 1);
    g_sw[p] = make_float2(__int_as_float(s), g_dinv[s] * g_dinv[d]);
}

// ---------------- weight conversion: Wt[l][n][k] = half(W_l[k][n]) ----------------
__global__ void convert_w3(const float* __restrict__ W1,
                           const float* __restrict__ W2,
                           const float* __restrict__ W3) {
    int i = blockIdx.x * blockDim.x + threadIdx.x;
    if (i >= 3 * FD * FD) return;
    int l = i / (FD * FD);
    int j = i % (FD * FD);
    const float* W = (l == 0) ? W1 : (l == 1) ? W2 : W3;
    int k = j >> 7, n = j & 127;
    g_Wt[l * FD * FD + n * FD + k] = __float2half_rn(W[j]);
}

// ---------------- tensor-core GEMM: Th = half(A @ W) ----------------
// 512 threads, 16 warps (4x4), warp tile 32x32, M-tile 128, full K=128 in smem.
#define AS_STRIDE 136
__global__ void __launch_bounds__(512) gemm_h(const float* __restrict__ Xf, int wsel) {
    __shared__ __align__(16) __half As[128 * AS_STRIDE];
    __shared__ __align__(16) __half Bs[128 * AS_STRIDE];

    const int tid  = threadIdx.x;
    const int warp = tid >> 5;
    const int lane = tid & 31;
    const int wm = warp >> 2;       // 0..3
    const int wn = warp & 3;        // 0..3
    const int row0 = blockIdx.x * 128;
    const int gr = lane >> 2;       // 0..7
    const int ck = (lane & 3) * 2;  // 0,2,4,6
    const __half* Wt = g_Wt + wsel * FD * FD;

    // load A [128 x 128]
    if (Xf != nullptr) {
#pragma unroll
        for (int it = 0; it < 8; it++) {
            int i = tid + it * 512;          // float4 slot, 0..4095
            int r = i >> 5, c4 = i & 31;
            float4 v = make_float4(0.f, 0.f, 0.f, 0.f);
            if (row0 + r < NN)
                v = *(const float4*)(Xf + (size_t)(row0 + r) * FD + c4 * 4);
            __half2 h0 = __floats2half2_rn(v.x, v.y);
            __half2 h1 = __floats2half2_rn(v.z, v.w);
            uint2 u;
            u.x = *(unsigned int*)&h0;
            u.y = *(unsigned int*)&h1;
            *(uint2*)(As + r * AS_STRIDE + c4 * 4) = u;
        }
    } else {
#pragma unroll
        for (int it = 0; it < 4; it++) {
            int i = tid + it * 512;          // uint4 slot, 0..2047
            int r = i >> 4, kq = i & 15;
            uint4 v = make_uint4(0u, 0u, 0u, 0u);
            if (row0 + r < NN)
                v = *(const uint4*)(g_Xh + (size_t)(row0 + r) * FD + kq * 8);
            *(uint4*)(As + r * AS_STRIDE + kq * 8) = v;
        }
    }
    // load B [128 x 128]: Bs[n][k] = Wt[n][k]
#pragma unroll
    for (int it = 0; it < 4; it++) {
        int i = tid + it * 512;
        int nr = i >> 4, kq = i & 15;
        *(uint4*)(Bs + nr * AS_STRIDE + kq * 8) =
            *(const uint4*)(Wt + nr * FD + kq * 8);
    }
    __syncthreads();

    float c[2][4][4];
#pragma unroll
    for (int mi = 0; mi < 2; mi++)
#pragma unroll
        for (int ni = 0; ni < 4; ni++)
#pragma unroll
            for (int q = 0; q < 4; q++) c[mi][ni][q] = 0.0f;

#pragma unroll
    for (int kk = 0; kk < 8; kk++) {
        int kb = kk * 16;
        unsigned int a[2][4];
#pragma unroll
        for (int mi = 0; mi < 2; mi++) {
            const __half* base = As + (wm * 32 + mi * 16 + gr) * AS_STRIDE + kb + ck;
            a[mi][0] = *(const unsigned int*)(base);
            a[mi][1] = *(const unsigned int*)(base + 8 * AS_STRIDE);
            a[mi][2] = *(const unsigned int*)(base + 8);
            a[mi][3] = *(const unsigned int*)(base + 8 * AS_STRIDE + 8);
        }
#pragma unroll
        for (int ni = 0; ni < 4; ni++) {
            const __half* bb = Bs + (wn * 32 + ni * 8 + gr) * AS_STRIDE + kb + ck;
            unsigned int b0 = *(const unsigned int*)(bb);
            unsigned int b1 = *(const unsigned int*)(bb + 8);
#pragma unroll
            for (int mi = 0; mi < 2; mi++) {
                asm volatile(
                    "mma.sync.aligned.m16n8k16.row.col.f32.f16.f16.f32 "
                    "{%0,%1,%2,%3}, {%4,%5,%6,%7}, {%8,%9}, {%0,%1,%2,%3};"
                    : "+f"(c[mi][ni][0]), "+f"(c[mi][ni][1]),
                      "+f"(c[mi][ni][2]), "+f"(c[mi][ni][3])
                    : "r"(a[mi][0]), "r"(a[mi][1]), "r"(a[mi][2]), "r"(a[mi][3]),
                      "r"(b0), "r"(b1));
            }
        }
    }

    const int cc = (lane & 3) * 2;
#pragma unroll
    for (int mi = 0; mi < 2; mi++) {
#pragma unroll
        for (int ni = 0; ni < 4; ni++) {
            int row = row0 + wm * 32 + mi * 16 + gr;
            int col = wn * 32 + ni * 8 + cc;
            if (row < NN) {
                __half2 h0 = __floats2half2_rn(c[mi][ni][0], c[mi][ni][1]);
                *(unsigned int*)(g_Th + (size_t)row * FD + col) = *(unsigned int*)&h0;
            }
            if (row + 8 < NN) {
                __half2 h1 = __floats2half2_rn(c[mi][ni][2], c[mi][ni][3]);
                *(unsigned int*)(g_Th + (size_t)(row + 8) * FD + col) = *(unsigned int*)&h1;
            }
        }
    }
}

// ---------------- fused aggregation: half-warp per node ----------------
__device__ __forceinline__ void acc8(float* a, uint4 u, float w) {
    __half2 h; float2 f;
    h = *(__half2*)&u.x; f = __half22float2(h);
    a[0] = fmaf(f.x, w, a[0]); a[1] = fmaf(f.y, w, a[1]);
    h = *(__half2*)&u.y; f = __half22float2(h);
    a[2] = fmaf(f.x, w, a[2]); a[3] = fmaf(f.y, w, a[3]);
    h = *(__half2*)&u.z; f = __half22float2(h);
    a[4] = fmaf(f.x, w, a[4]); a[5] = fmaf(f.y, w, a[5]);
    h = *(__half2*)&u.w; f = __half22float2(h);
    a[6] = fmaf(f.x, w, a[6]); a[7] = fmaf(f.y, w, a[7]);
}

// mode 0: write relu(acc) half -> g_Xh; mode 1: write acc half (no relu) -> g_Xh
__global__ void __launch_bounds__(256) aggregate(int mode, const float* __restrict__ bias) {
    int gwarp = (blockIdx.x * 256 + threadIdx.x) >> 5;
    int lane = threadIdx.x & 31;
    int node = gwarp * 2 + (lane >> 4);
    int ln = lane & 15;
    if (node >= NN) return;
    int beg = g_rowptr[node], end = g_rowptr[node + 1];
    float di = g_dinv[node];
    float cnorm = di * di;

    float a[8];
    {
        float4 b0 = *(const float4*)(bias + ln * 8);
        float4 b1 = *(const float4*)(bias + ln * 8 + 4);
        a[0] = b0.x; a[1] = b0.y; a[2] = b0.z; a[3] = b0.w;
        a[4] = b1.x; a[5] = b1.y; a[6] = b1.z; a[7] = b1.w;
    }
    {
        uint4 u = *(const uint4*)(g_Th + (size_t)node * FD + ln * 8);
        acc8(a, u, cnorm);
    }

    int i = beg;
    for (; i + 4 <= end; i += 4) {
        float2 e0 = g_sw[i + 0];
        float2 e1 = g_sw[i + 1];
        float2 e2 = g_sw[i + 2];
        float2 e3 = g_sw[i + 3];
        uint4 u0 = *(const uint4*)(g_Th + (size_t)__float_as_int(e0.x) * FD + ln * 8);
        uint4 u1 = *(const uint4*)(g_Th + (size_t)__float_as_int(e1.x) * FD + ln * 8);
        uint4 u2 = *(const uint4*)(g_Th + (size_t)__float_as_int(e2.x) * FD + ln * 8);
        uint4 u3 = *(const uint4*)(g_Th + (size_t)__float_as_int(e3.x) * FD + ln * 8);
        acc8(a, u0, e0.y);
        acc8(a, u1, e1.y);
        acc8(a, u2, e2.y);
        acc8(a, u3, e3.y);
    }
    for (; i < end; i++) {
        float2 e0 = g_sw[i];
        uint4 u0 = *(const uint4*)(g_Th + (size_t)__float_as_int(e0.x) * FD + ln * 8);
        acc8(a, u0, e0.y);
    }

    if (mode == 0) {
#pragma unroll
        for (int q = 0; q < 8; q++) a[q] = fmaxf(a[q], 0.f);
    }
    __half2 h0 = __floats2half2_rn(a[0], a[1]);
    __half2 h1 = __floats2half2_rn(a[2], a[3]);
    __half2 h2 = __floats2half2_rn(a[4], a[5]);
    __half2 h3 = __floats2half2_rn(a[6], a[7]);
    uint4 u;
    u.x = *(unsigned int*)&h0;
    u.y = *(unsigned int*)&h1;
    u.z = *(unsigned int*)&h2;
    u.w = *(unsigned int*)&h3;
    *(uint4*)(g_Xh + (size_t)node * FD + ln * 8) = u;
}

// ---------------- pooling (reads half activations) ----------------
__global__ void __launch_bounds__(128) pool_accum(const void* __restrict__ batch, int n) {
    __shared__ int sb[256];
    int f  = threadIdx.x;
    int v0 = blockIdx.x * 256;
    for (int i = f; i < 256; i += 128) {
        int v = v0 + i;
        sb[i] = (v < n) ? batch_at(batch, v) : -1;
    }
    __syncthreads();
    float acc = 0.f, ccnt = 0.f;
    int curg = -1;
    for (int i = 0; i < 256; i++) {
        int g = sb[i];
        if (g < 0) break;
        if (g != curg) {
            if (curg >= 0) {
                atomicAdd(&g_sums[curg * FD + f], acc);
                if (f == 0) atomicAdd(&g_cnt[curg], ccnt);
            }
            acc = 0.f; ccnt = 0.f; curg = g;
        }
        acc  += __half2float(g_Xh[(size_t)(v0 + i) * FD + f]);
        ccnt += 1.f;
    }
    if (curg >= 0) {
        atomicAdd(&g_sums[curg * FD + f], acc);
        if (f == 0) atomicAdd(&g_cnt[curg], ccnt);
    }
}

// ---------------- finalize ----------------
__global__ void __launch_bounds__(128) finalize(
    const float* __restrict__ Wlin, const float* __restrict__ blin,
    float* __restrict__ out, int out_size)
{
    int g = blockIdx.x;
    int f = threadIdx.x;
    __shared__ float se[FD];
    float e = g_sums[g * FD + f] / fmaxf(g_cnt[g], 1.0f);
    se[f] = e;
    if (out_size >= NG * NC + NG * FD)
        out[NG * NC + g * FD + f] = e;
    __syncthreads();
    if (f < NC) {
        float s = blin[f];
#pragma unroll
        for (int k = 0; k < FD; k++)
            s = fmaf(se[k], Wlin[k * NC + f], s);
        out[g * NC + f] = s;
    }
}

// ---------------- launch ----------------
extern "C" void kernel_launch(void* const* d_in, const int* in_sizes, int n_in,
                              void* d_out, int out_size) {
    const float* x    = (const float*)d_in[0];
    const void*  ei   = d_in[1];
    const void*  batch= d_in[2];
    const float* W1   = (const float*)d_in[3];
    const float* b1   = (const float*)d_in[4];
    const float* W2   = (const float*)d_in[5];
    const float* b2   = (const float*)d_in[6];
    const float* W3   = (const float*)d_in[7];
    const float* b3   = (const float*)d_in[8];
    const float* Wlin = (const float*)d_in[9];
    const float* blin = (const float*)d_in[10];
    float* out = (float*)d_out;
    const int n = NN;

    const int gemm_grid = (NN + 127) / 128;
    const int agg_grid  = (NN * 16 + 255) / 256;

    detect_i64 <<<1, 256>>>((const int*)batch);                 // 0
    zero_init  <<<(NN + 255) / 256, 256>>>();                   // 1
    convert_w3 <<<(3 * FD * FD + 255) / 256, 256>>>(W1, W2, W3);// 2
    gemm_h     <<<gemm_grid, 512>>>(x, 0);                      // 3 (profiled)
    count_edges<<<(NE + 255) / 256, 256>>>(ei);                 // 4
    dinv_k     <<<(NN + 255) / 256, 256>>>();                   // 5
    scan1      <<<SCAN_BLOCKS, 256>>>();
    scan2      <<<1, 128>>>();
    scan3      <<<SCAN_BLOCKS, 256>>>();
    fill_csr   <<<(NE + 255) / 256, 256>>>(ei);

    aggregate  <<<agg_grid, 256>>>(0, b1);     // -> relu half Xh
    gemm_h     <<<gemm_grid, 512>>>(nullptr, 1);
    aggregate  <<<agg_grid, 256>>>(0, b2);     // -> relu half Xh
    gemm_h     <<<gemm_grid, 512>>>(nullptr, 2);
    aggregate  <<<agg_grid, 256>>>(1, b3);     // -> half Xh (no relu)

    pool_accum<<<(NN + 255) / 256, 128>>>(batch, n);
    finalize  <<<NG, 128>>>(Wlin, blin, out, out_size);
}